// round 8
// baseline (speedup 1.0000x reference)
#include <cuda_runtime.h>
#include <cuda_fp16.h>
#include <math.h>
#include <stdint.h>

// ---------------- shapes -----------------------------------------------------
#define T_ 4
#define B_ 16
#define C_ 256
#define N_ 1024
#define HD_ 1024
#define HEADS_ 8
#define TB_ (T_*B_)

#define S_C   ((size_t)B_*N_*C_)        // 4,194,304
#define S_QKV ((size_t)B_*N_*768)       // 12,582,912
#define S_H   ((size_t)B_*N_*HD_)       // 16,777,216
#define TCN   ((size_t)T_*S_C)
#define TQKV  ((size_t)T_*S_QKV)
#define THN   ((size_t)T_*S_H)

#define WR_ROWS 1792
#define WR_SZ   (WR_ROWS*256)           // 458752
#define AOFF_QKV  0
#define AOFF_P    768
#define AOFF_F1   1024
#define AOFF_F2   2048
#define ATOT      2304

// ---------------- device scratch ---------------------------------------------
__device__ __half g_wr  [2][WR_SZ];     // fp16 2-split (qkv + fc1 weights)
__device__ __half g_wpb [2][65536];     // fp16 2-split proj weights
__device__ __half g_wf2b[2][262144];    // fp16 2-split fc2 weights
__device__ float g_alpha[ATOT], g_off[ATOT], g_beta[ATOT];

__device__ float  g_xt  [TCN];          // x [tb][n][c] fp32
__device__ __half g_xsp [2][TCN];       // x fp16 2-split
__device__ __half g_qkvh[TQKV];         // qkv spikes fp16 [tb][n][768]
__device__ float  g_a   [TCN];          // attn values
__device__ __half g_ab  [TCN];          // attn spikes fp16
__device__ float  g_x1  [TCN];          // x + attn spikes
__device__ __half g_ps  [2][TCN];       // x1 fp16 2-split
__device__ __half g_h1b [THN];          // fc1 spikes fp16
__device__ float  g_y2  [TCN];          // fc2 preact

// ---------------- helpers ----------------------------------------------------
__device__ __forceinline__ uint32_t smem_u32(const void* p) {
    uint32_t a;
    asm("{ .reg .u64 t; cvta.to.shared.u64 t, %1; cvt.u32.u64 %0, t; }" : "=r"(a) : "l"(p));
    return a;
}
#define CP_ASYNC16(dst, src) \
    asm volatile("cp.async.cg.shared.global [%0], [%1], 16;\n" :: "r"(dst), "l"(src))
#define CP_COMMIT() asm volatile("cp.async.commit_group;\n" ::: "memory")
#define CP_WAIT(n)  asm volatile("cp.async.wait_group %0;\n" :: "n"(n) : "memory")

__device__ __forceinline__ void split2h(float x, __half& a, __half& b) {
    a = __float2half_rn(x); float r = x - __half2float(a);
    b = __float2half_rn(r);
}

__device__ __forceinline__ void mma_f16(float* c, const uint32_t* a, const uint32_t* b) {
    asm volatile("mma.sync.aligned.m16n8k16.row.col.f32.f16.f16.f32 "
        "{%0,%1,%2,%3}, {%4,%5,%6,%7}, {%8,%9}, {%0,%1,%2,%3};"
        : "+f"(c[0]), "+f"(c[1]), "+f"(c[2]), "+f"(c[3])
        : "r"(a[0]), "r"(a[1]), "r"(a[2]), "r"(a[3]), "r"(b[0]), "r"(b[1]));
}

// ---------------- prep kernels -----------------------------------------------
__global__ void prep_aff(const float* __restrict__ bn_q, const float* __restrict__ bn_k,
                         const float* __restrict__ bn_v, const float* __restrict__ b_proj,
                         const float* __restrict__ bn_proj, const float* __restrict__ b_fc1,
                         const float* __restrict__ bn_fc1, const float* __restrict__ b_fc2,
                         const float* __restrict__ bn_fc2)
{
    for (int i = threadIdx.x; i < ATOT; i += blockDim.x) {
        const float* bn; const float* bias = 0; int Cn, ch;
        if (i < 256)       { bn = bn_q;    Cn = 256;  ch = i; }
        else if (i < 512)  { bn = bn_k;    Cn = 256;  ch = i - 256; }
        else if (i < 768)  { bn = bn_v;    Cn = 256;  ch = i - 512; }
        else if (i < 1024) { bn = bn_proj; Cn = 256;  ch = i - 768;  bias = b_proj; }
        else if (i < 2048) { bn = bn_fc1;  Cn = 1024; ch = i - 1024; bias = b_fc1; }
        else               { bn = bn_fc2;  Cn = 256;  ch = i - 2048; bias = b_fc2; }
        float g = bn[0*Cn+ch], be = bn[1*Cn+ch], m = bn[2*Cn+ch], va = bn[3*Cn+ch];
        float rs = (float)(1.0 / sqrt((double)va + 1e-5));
        g_alpha[i] = g * rs;
        g_off[i]   = (bias ? bias[ch] : 0.0f) - m;
        g_beta[i]  = be;
    }
}

__global__ void prep_w_real(const float* __restrict__ wq, const float* __restrict__ wk,
                            const float* __restrict__ wv, const float* __restrict__ wf1)
{
    int i = blockIdx.x * 256 + threadIdx.x;
    if (i >= WR_SZ) return;
    int row = i >> 8, k = i & 255;
    float w;
    if (row < 256)       w = wq[row*256 + k];
    else if (row < 512)  w = wk[(row-256)*256 + k];
    else if (row < 768)  w = wv[(row-512)*256 + k];
    else                 w = wf1[(row-768)*256 + k];
    split2h(w, g_wr[0][i], g_wr[1][i]);
}

__global__ void prep_w_bin(const float* __restrict__ wp, const float* __restrict__ wf2)
{
    int i = blockIdx.x * 256 + threadIdx.x;
    if (i >= 65536 + 262144) return;
    if (i < 65536) split2h(wp[i], g_wpb[0][i], g_wpb[1][i]);
    else { int j = i - 65536; split2h(wf2[j], g_wf2b[0][j], g_wf2b[1][j]); }
}

// x [tb][c][n] -> g_xt [tb][n][c] fp32 + fp16 2-split
__global__ void transpose_split(const float* __restrict__ x)
{
    __shared__ float tile[32][33];
    int c0 = blockIdx.x * 32, n0 = blockIdx.y * 32, tb = blockIdx.z;
    int tx = threadIdx.x & 31, ty = threadIdx.x >> 5;
    const float* xb = x + (size_t)tb * C_ * N_;
    #pragma unroll
    for (int j = 0; j < 4; j++)
        tile[ty + 8*j][tx] = xb[(size_t)(c0 + ty + 8*j) * N_ + n0 + tx];
    __syncthreads();
    #pragma unroll
    for (int j = 0; j < 4; j++) {
        int n = n0 + ty + 8*j, c = c0 + tx;
        float v = tile[tx][ty + 8*j];
        size_t idx = ((size_t)tb * N_ + n) * C_ + c;
        g_xt[idx] = v;
        split2h(v, g_xsp[0][idx], g_xsp[1][idx]);
    }
}

// ---------------- fused GEMM + BN + LIF (t-sequential) ------------------------
// blockIdx.z = b (batch). CTA loops t=0..3, keeps LIF membrane v in registers,
// emits spikes directly:
//   EPI=0: OutH[(tb*N+n)*Mtot+m] = spike (fp16)
//   EPI=1: proj epilogue: x1 = g_xt + spike -> g_x1 (fp32) + g_ps fp16 2-split
// Same mainloop / K-ordering as the passing R7 kernel (corrections first).
template<int KTOT, int NT, int EPI>
__global__ __launch_bounds__(256)
void gemm_lif(const __half* __restrict__ Act, size_t actStride,
              const __half* __restrict__ Wt, size_t wStride,
              __half* __restrict__ OutH, int Mtot,
              const float* __restrict__ alpha, const float* __restrict__ offv,
              const float* __restrict__ beta)
{
    constexpr int KC   = KTOT / 32;
    constexpr int NSEG = NT * KC;
    constexpr int PITCH  = 80;
    constexpr int TILEB  = 128 * PITCH;
    constexpr int STAGEB = 2 * TILEB;

    extern __shared__ char smem[];
    const uint32_t sb = smem_u32(smem);
    const int tid  = threadIdx.x;
    const int lane = tid & 31, warp = tid >> 5;
    const int wn = warp & 1, wm = warp >> 1;
    const int n0 = blockIdx.x * 128, m0 = blockIdx.y * 128;
    const int bz = blockIdx.z;          // batch index

    const int WA3[3] = {1,0,0};
    const int XB3[3] = {0,1,0};
    const int WA2[2] = {1,0};
    const int XB2[2] = {0,0};

    const int r_ = tid >> 2, c_ = tid & 3;

    int tb = bz;
    auto load = [&](int seg, int st) {
        if (seg < NSEG) {
            int term = seg / KC, kc = seg - term * KC;
            int wa = (NT == 3) ? WA3[term] : WA2[term];
            int xb = (NT == 3) ? XB3[term] : XB2[term];
            const __half* ap = Act + (size_t)xb * actStride
                          + ((size_t)tb * N_ + n0) * KTOT + kc * 32;
            const __half* wp = Wt + (size_t)wa * wStride + (size_t)m0 * KTOT + kc * 32;
            uint32_t ab = sb + st * STAGEB, bbs = ab + TILEB;
            #pragma unroll
            for (int j = 0; j < 2; j++) {
                int r = r_ + j * 64;
                CP_ASYNC16(ab  + r * PITCH + c_ * 16, ap + (size_t)r * KTOT + c_ * 8);
                CP_ASYNC16(bbs + r * PITCH + c_ * 16, wp + (size_t)r * KTOT + c_ * 8);
            }
        }
        CP_COMMIT();
    };

    float vmem[4][4][4];
    #pragma unroll
    for (int i = 0; i < 4; i++)
        #pragma unroll
        for (int j = 0; j < 4; j++)
            #pragma unroll
            for (int v = 0; v < 4; v++) vmem[i][j][v] = 0.0f;

    const int group = lane >> 2, tig = lane & 3;

    for (int t = 0; t < T_; t++) {
        tb = t * B_ + bz;

        float acc[4][4][4];
        #pragma unroll
        for (int i = 0; i < 4; i++)
            #pragma unroll
            for (int j = 0; j < 4; j++)
                #pragma unroll
                for (int v = 0; v < 4; v++) acc[i][j][v] = 0.0f;

        load(0, 0);
        load(1, 1);

        for (int seg = 0; seg < NSEG; ++seg) {
            CP_WAIT(1);
            __syncthreads();
            load(seg + 2, (seg + 2) % 3);

            uint32_t ab = sb + (seg % 3) * STAGEB, bbs = ab + TILEB;
            #pragma unroll
            for (int ki = 0; ki < 2; ki++) {
                uint32_t a[4][4];
                #pragma unroll
                for (int ni = 0; ni < 4; ni++) {
                    int row = wn * 64 + ni * 16 + (lane & 15);
                    int cc  = ki * 2 + (lane >> 4);
                    uint32_t ad = ab + row * PITCH + cc * 16;
                    asm volatile("ldmatrix.sync.aligned.m8n8.x4.shared.b16 {%0,%1,%2,%3}, [%4];"
                        : "=r"(a[ni][0]), "=r"(a[ni][1]), "=r"(a[ni][2]), "=r"(a[ni][3])
                        : "r"(ad));
                }
                uint32_t b[4][2];
                #pragma unroll
                for (int mi2 = 0; mi2 < 2; mi2++) {
                    int row = wm * 32 + mi2 * 16 + (lane & 7) + ((lane >> 4) << 3);
                    int cc  = ki * 2 + ((lane >> 3) & 1);
                    uint32_t bd = bbs + row * PITCH + cc * 16;
                    uint32_t r0, r1, r2, r3;
                    asm volatile("ldmatrix.sync.aligned.m8n8.x4.shared.b16 {%0,%1,%2,%3}, [%4];"
                        : "=r"(r0), "=r"(r1), "=r"(r2), "=r"(r3) : "r"(bd));
                    b[mi2*2+0][0] = r0; b[mi2*2+0][1] = r1;
                    b[mi2*2+1][0] = r2; b[mi2*2+1][1] = r3;
                }
                #pragma unroll
                for (int ni = 0; ni < 4; ni++)
                    #pragma unroll
                    for (int mi = 0; mi < 4; mi++)
                        mma_f16(acc[ni][mi], a[ni], b[mi]);
            }
        }
        __syncthreads();   // all smem reads done before next t overwrites stages

        // ---- fused BN + LIF epilogue for this t ----
        #pragma unroll
        for (int mi = 0; mi < 4; mi++) {
            int m = m0 + wm * 32 + mi * 8 + tig * 2;
            float2 al = *(const float2*)&alpha[m];
            float2 of = *(const float2*)&offv[m];
            float2 be = *(const float2*)&beta[m];
            #pragma unroll
            for (int ni = 0; ni < 4; ni++)
                #pragma unroll
                for (int vv = 0; vv < 2; vv++) {
                    int n = n0 + wn * 64 + ni * 16 + group + vv * 8;
                    float p0 = al.x * (acc[ni][mi][vv*2+0] + of.x) + be.x;
                    float p1 = al.y * (acc[ni][mi][vv*2+1] + of.y) + be.y;
                    float v0 = vmem[ni][mi][vv*2+0];
                    float v1 = vmem[ni][mi][vv*2+1];
                    v0 = (v0 + p0) * 0.5f;
                    v1 = (v1 + p1) * 0.5f;
                    float s0 = (v0 >= 1.0f) ? 1.0f : 0.0f;
                    float s1 = (v1 >= 1.0f) ? 1.0f : 0.0f;
                    if (s0 != 0.0f) v0 = 0.0f;
                    if (s1 != 0.0f) v1 = 0.0f;
                    vmem[ni][mi][vv*2+0] = v0;
                    vmem[ni][mi][vv*2+1] = v1;
                    if (EPI == 0) {
                        *(__half2*)&OutH[((size_t)tb * N_ + n) * Mtot + m] =
                            __floats2half2_rn(s0, s1);
                    } else {
                        size_t idx = ((size_t)tb * N_ + n) * C_ + m;
                        float2 xx = *(const float2*)&g_xt[idx];
                        float X0 = xx.x + s0, X1 = xx.y + s1;
                        *(float2*)&g_x1[idx] = make_float2(X0, X1);
                        __half h00, h01, h10, h11;
                        split2h(X0, h00, h01);
                        split2h(X1, h10, h11);
                        *(__half2*)&g_ps[0][idx] = __halves2half2(h00, h10);
                        *(__half2*)&g_ps[1][idx] = __halves2half2(h01, h11);
                    }
                }
        }
    }
}

// ---------------- unfused GEMM (fc2) ------------------------------------------
template<int KTOT, int NT>
__global__ __launch_bounds__(256)
void gemm_mma(const __half* __restrict__ Act, size_t actStride,
              const __half* __restrict__ Wt, size_t wStride,
              float* __restrict__ Y, int Mtot,
              const float* __restrict__ alpha, const float* __restrict__ offv,
              const float* __restrict__ beta)
{
    constexpr int KC   = KTOT / 32;
    constexpr int NSEG = NT * KC;
    constexpr int PITCH  = 80;
    constexpr int TILEB  = 128 * PITCH;
    constexpr int STAGEB = 2 * TILEB;

    extern __shared__ char smem[];
    const uint32_t sb = smem_u32(smem);
    const int tid  = threadIdx.x;
    const int lane = tid & 31, warp = tid >> 5;
    const int wn = warp & 1, wm = warp >> 1;
    const int n0 = blockIdx.x * 128, m0 = blockIdx.y * 128;
    const int tbz = blockIdx.z;

    const int WA2[2] = {1,0};
    const int r_ = tid >> 2, c_ = tid & 3;

    auto load = [&](int seg, int st) {
        if (seg < NSEG) {
            int term = seg / KC, kc = seg - term * KC;
            int wa = WA2[term];
            const __half* ap = Act + ((size_t)tbz * N_ + n0) * KTOT + kc * 32;
            const __half* wp = Wt + (size_t)wa * wStride + (size_t)m0 * KTOT + kc * 32;
            uint32_t ab = sb + st * STAGEB, bbs = ab + TILEB;
            #pragma unroll
            for (int j = 0; j < 2; j++) {
                int r = r_ + j * 64;
                CP_ASYNC16(ab  + r * PITCH + c_ * 16, ap + (size_t)r * KTOT + c_ * 8);
                CP_ASYNC16(bbs + r * PITCH + c_ * 16, wp + (size_t)r * KTOT + c_ * 8);
            }
        }
        CP_COMMIT();
    };

    float acc[4][4][4];
    #pragma unroll
    for (int i = 0; i < 4; i++)
        #pragma unroll
        for (int j = 0; j < 4; j++)
            #pragma unroll
            for (int v = 0; v < 4; v++) acc[i][j][v] = 0.0f;

    load(0, 0);
    load(1, 1);

    for (int seg = 0; seg < NSEG; ++seg) {
        CP_WAIT(1);
        __syncthreads();
        load(seg + 2, (seg + 2) % 3);

        uint32_t ab = sb + (seg % 3) * STAGEB, bbs = ab + TILEB;
        #pragma unroll
        for (int ki = 0; ki < 2; ki++) {
            uint32_t a[4][4];
            #pragma unroll
            for (int ni = 0; ni < 4; ni++) {
                int row = wn * 64 + ni * 16 + (lane & 15);
                int cc  = ki * 2 + (lane >> 4);
                uint32_t ad = ab + row * PITCH + cc * 16;
                asm volatile("ldmatrix.sync.aligned.m8n8.x4.shared.b16 {%0,%1,%2,%3}, [%4];"
                    : "=r"(a[ni][0]), "=r"(a[ni][1]), "=r"(a[ni][2]), "=r"(a[ni][3])
                    : "r"(ad));
            }
            uint32_t b[4][2];
            #pragma unroll
            for (int mi2 = 0; mi2 < 2; mi2++) {
                int row = wm * 32 + mi2 * 16 + (lane & 7) + ((lane >> 4) << 3);
                int cc  = ki * 2 + ((lane >> 3) & 1);
                uint32_t bd = bbs + row * PITCH + cc * 16;
                uint32_t r0, r1, r2, r3;
                asm volatile("ldmatrix.sync.aligned.m8n8.x4.shared.b16 {%0,%1,%2,%3}, [%4];"
                    : "=r"(r0), "=r"(r1), "=r"(r2), "=r"(r3) : "r"(bd));
                b[mi2*2+0][0] = r0; b[mi2*2+0][1] = r1;
                b[mi2*2+1][0] = r2; b[mi2*2+1][1] = r3;
            }
            #pragma unroll
            for (int ni = 0; ni < 4; ni++)
                #pragma unroll
                for (int mi = 0; mi < 4; mi++)
                    mma_f16(acc[ni][mi], a[ni], b[mi]);
        }
    }

    const int group = lane >> 2, tig = lane & 3;
    #pragma unroll
    for (int mi = 0; mi < 4; mi++) {
        int m = m0 + wm * 32 + mi * 8 + tig * 2;
        float2 al = *(const float2*)&alpha[m];
        float2 of = *(const float2*)&offv[m];
        float2 be = *(const float2*)&beta[m];
        #pragma unroll
        for (int ni = 0; ni < 4; ni++)
            #pragma unroll
            for (int v = 0; v < 2; v++) {
                int n = n0 + wn * 64 + ni * 16 + group + v * 8;
                float2 val;
                val.x = al.x * (acc[ni][mi][v*2+0] + of.x) + be.x;
                val.y = al.y * (acc[ni][mi][v*2+1] + of.y) + be.y;
                *(float2*)&Y[((size_t)tbz * N_ + n) * Mtot + m] = val;
            }
    }
}

// ---------------- LIF kernels (remaining) -------------------------------------
__global__ void lif_to_half(const float* __restrict__ y, __half* __restrict__ o,
                            size_t S, float vth)
{
    size_t i = (size_t)blockIdx.x * blockDim.x + threadIdx.x;
    if (i >= S) return;
    float v = 0.0f;
    #pragma unroll
    for (int t = 0; t < T_; t++) {
        size_t idx = (size_t)t * S + i;
        float xx = y[idx];
        v = v + (xx - v) * 0.5f;
        float s = (v >= vth) ? 1.0f : 0.0f;
        o[idx] = __float2half_rn(s);
        if (s != 0.0f) v = 0.0f;
    }
}
// out[t,b,c,n] = x1 + spike(y2); internal buffers are [tb][n][c]
__global__ void lif_final(float* __restrict__ out, size_t S)
{
    size_t i = (size_t)blockIdx.x * blockDim.x + threadIdx.x;
    if (i >= S) return;
    int b = (int)(i / ((size_t)N_ * C_));
    int r = (int)(i % ((size_t)N_ * C_));
    int n = r >> 8, c = r & 255;
    float v = 0.0f;
    #pragma unroll
    for (int t = 0; t < T_; t++) {
        size_t idx = (size_t)t * S + i;
        float xx = g_y2[idx];
        v = v + (xx - v) * 0.5f;
        float s = (v >= 1.0f) ? 1.0f : 0.0f;
        out[(((size_t)t * B_ + b) * C_ + c) * N_ + n] = g_x1[idx] + s;
        if (s != 0.0f) v = 0.0f;
    }
}

// ---------------- attention (exact integer-valued fp32; half spike inputs) ----
__global__ __launch_bounds__(256) void attn_kernel()
{
    int h  = blockIdx.x & 7;
    int tb = blockIdx.x >> 3;
    const __half* base = g_qkvh + (size_t)tb * N_ * 768;

    __shared__ float ks[128][33];
    __shared__ float vs[128][36];
    __shared__ float kvs[32][33];

    int tid = threadIdx.x;
    int d  = tid >> 3;
    int e4 = (tid & 7) * 4;
    float acc[4] = {0.f, 0.f, 0.f, 0.f};

    for (int n0 = 0; n0 < N_; n0 += 128) {
        for (int i = tid; i < 128 * 32; i += 256) {
            int nl = i >> 5, dd = i & 31;
            const __half* row = base + (size_t)(n0 + nl) * 768 + h * 32;
            ks[nl][dd] = __half2float(row[256 + dd]);
            vs[nl][dd] = __half2float(row[512 + dd]);
        }
        __syncthreads();
        for (int n = 0; n < 128; n++) {
            float kd = ks[n][d];
            float4 vv = *(const float4*)&vs[n][e4];
            acc[0] += kd * vv.x; acc[1] += kd * vv.y;
            acc[2] += kd * vv.z; acc[3] += kd * vv.w;
        }
        __syncthreads();
    }
    kvs[d][e4+0] = acc[0]; kvs[d][e4+1] = acc[1];
    kvs[d][e4+2] = acc[2]; kvs[d][e4+3] = acc[3];
    __syncthreads();

    for (int n = tid; n < N_; n += 256) {
        const __half* qrow = base + (size_t)n * 768 + h * 32;
        float a[32];
        #pragma unroll
        for (int e = 0; e < 32; e++) a[e] = 0.0f;
        #pragma unroll
        for (int dd = 0; dd < 32; dd++) {
            if (__half2float(qrow[dd]) != 0.0f) {
                #pragma unroll
                for (int e = 0; e < 32; e++) a[e] += kvs[dd][e];
            }
        }
        float* ao = g_a + ((size_t)tb * N_ + n) * C_ + h * 32;
        #pragma unroll
        for (int e = 0; e < 32; e += 4) {
            float4 w;
            w.x = a[e]*0.125f; w.y = a[e+1]*0.125f;
            w.z = a[e+2]*0.125f; w.w = a[e+3]*0.125f;
            *(float4*)(ao + e) = w;
        }
    }
}

// ---------------- launch -----------------------------------------------------
extern "C" void kernel_launch(void* const* d_in, const int* in_sizes, int n_in,
                              void* d_out, int out_size)
{
    const float* x       = (const float*)d_in[0];
    const float* wq      = (const float*)d_in[2];
    const float* bn_q    = (const float*)d_in[3];
    const float* wk      = (const float*)d_in[4];
    const float* bn_k    = (const float*)d_in[5];
    const float* wv      = (const float*)d_in[6];
    const float* bn_v    = (const float*)d_in[7];
    const float* w_proj  = (const float*)d_in[8];
    const float* b_proj  = (const float*)d_in[9];
    const float* bn_proj = (const float*)d_in[10];
    const float* w_fc1   = (const float*)d_in[11];
    const float* b_fc1   = (const float*)d_in[12];
    const float* bn_fc1  = (const float*)d_in[13];
    const float* w_fc2   = (const float*)d_in[14];
    const float* b_fc2   = (const float*)d_in[15];
    const float* bn_fc2  = (const float*)d_in[16];
    float* out = (float*)d_out;

    __half *wr, *xsp, *ps, *wpb, *wf2b, *ab, *h1b, *qkvh;
    float *a, *y2, *al, *of, *be;
    cudaGetSymbolAddress((void**)&wr,   g_wr);
    cudaGetSymbolAddress((void**)&wpb,  g_wpb);
    cudaGetSymbolAddress((void**)&wf2b, g_wf2b);
    cudaGetSymbolAddress((void**)&xsp,  g_xsp);
    cudaGetSymbolAddress((void**)&ps,   g_ps);
    cudaGetSymbolAddress((void**)&ab,   g_ab);
    cudaGetSymbolAddress((void**)&h1b,  g_h1b);
    cudaGetSymbolAddress((void**)&qkvh, g_qkvh);
    cudaGetSymbolAddress((void**)&a,    g_a);
    cudaGetSymbolAddress((void**)&y2,   g_y2);
    cudaGetSymbolAddress((void**)&al,   g_alpha);
    cudaGetSymbolAddress((void**)&of,   g_off);
    cudaGetSymbolAddress((void**)&be,   g_beta);

    const int SMEM = 3 * 20480;   // 61440
    cudaFuncSetAttribute(gemm_lif<256,3,0>,
                         cudaFuncAttributeMaxDynamicSharedMemorySize, SMEM);
    cudaFuncSetAttribute(gemm_lif<256,2,1>,
                         cudaFuncAttributeMaxDynamicSharedMemorySize, SMEM);
    cudaFuncSetAttribute(gemm_mma<1024,2>,
                         cudaFuncAttributeMaxDynamicSharedMemorySize, SMEM);

    prep_aff<<<1, 256>>>(bn_q, bn_k, bn_v, b_proj, bn_proj, b_fc1, bn_fc1, b_fc2, bn_fc2);
    prep_w_real<<<(WR_SZ + 255)/256, 256>>>(wq, wk, wv, w_fc1);
    prep_w_bin<<<(65536 + 262144 + 255)/256, 256>>>(w_proj, w_fc2);
    transpose_split<<<dim3(8, 32, TB_), 256>>>(x);

    // qkv: M=768, 3-term real input, fused LIF -> fp16 spikes
    gemm_lif<256,3,0><<<dim3(8, 6, B_), 256, SMEM>>>(
        xsp, TCN, wr, WR_SZ, qkvh, 768, al + AOFF_QKV, of + AOFF_QKV, be + AOFF_QKV);

    attn_kernel<<<TB_ * HEADS_, 256>>>();
    lif_to_half<<<(int)(S_C/256), 256>>>(a, ab, S_C, 0.5f);

    // proj: M=256, 2-term binary input, fused LIF + residual + split epilogue
    gemm_lif<256,2,1><<<dim3(8, 2, B_), 256, SMEM>>>(
        ab, 0, wpb, 65536, (/*unused*/__half*)nullptr, 256,
        al + AOFF_P, of + AOFF_P, be + AOFF_P);

    // fc1: M=1024, 3-term real input, fused LIF -> fp16 spikes
    gemm_lif<256,3,0><<<dim3(8, 8, B_), 256, SMEM>>>(
        ps, TCN, wr + 768*256, WR_SZ, h1b, 1024,
        al + AOFF_F1, of + AOFF_F1, be + AOFF_F1);

    // fc2: M=256, K=1024, 2-term binary input (unfused; transposed output in lif_final)
    gemm_mma<1024,2><<<dim3(8, 2, TB_), 256, SMEM>>>(
        h1b, 0, wf2b, 262144, y2, 256, al + AOFF_F2, of + AOFF_F2, be + AOFF_F2);
    lif_final<<<(int)(S_C/256), 256>>>(out, S_C);
}

// round 9
// speedup vs baseline: 1.1913x; 1.1913x over previous
#include <cuda_runtime.h>
#include <cuda_fp16.h>
#include <math.h>
#include <stdint.h>

// ---------------- shapes -----------------------------------------------------
#define T_ 4
#define B_ 16
#define C_ 256
#define N_ 1024
#define HD_ 1024
#define HEADS_ 8
#define TB_ (T_*B_)

#define S_C   ((size_t)B_*N_*C_)        // 4,194,304
#define S_QKV ((size_t)B_*N_*768)       // 12,582,912
#define S_H   ((size_t)B_*N_*HD_)       // 16,777,216
#define TCN   ((size_t)T_*S_C)
#define TQKV  ((size_t)T_*S_QKV)
#define THN   ((size_t)T_*S_H)

#define WR_ROWS 1792
#define WR_SZ   (WR_ROWS*256)           // 458752
#define AOFF_QKV  0
#define AOFF_P    768
#define AOFF_F1   1024
#define AOFF_F2   2048
#define ATOT      2304

// ---------------- device scratch ---------------------------------------------
__device__ __half g_wr  [2][WR_SZ];     // fp16 2-split (qkv + fc1 weights)
__device__ __half g_wpb [2][65536];     // fp16 2-split proj weights
__device__ __half g_wf2b[2][262144];    // fp16 2-split fc2 weights
__device__ float g_alpha[ATOT], g_off[ATOT], g_beta[ATOT];

__device__ float  g_xt  [TCN];          // x [tb][n][c] fp32
__device__ __half g_xsp [2][TCN];       // x fp16 2-split
__device__ float  g_qkv [TQKV];         // qkv preact fp32
__device__ __half g_qkvh[TQKV];         // qkv spikes fp16
__device__ float  g_a   [TCN];          // attn values
__device__ __half g_ab  [TCN];          // attn spikes fp16
__device__ float  g_p   [TCN];          // proj preact
__device__ float  g_x1  [TCN];          // x + attn spikes
__device__ __half g_ps  [2][TCN];       // x1 fp16 2-split
__device__ float  g_h1  [THN];          // fc1 preact
__device__ __half g_h1b [THN];          // fc1 spikes fp16
__device__ float  g_y2  [TCN];          // fc2 preact

// ---------------- helpers ----------------------------------------------------
__device__ __forceinline__ uint32_t smem_u32(const void* p) {
    uint32_t a;
    asm("{ .reg .u64 t; cvta.to.shared.u64 t, %1; cvt.u32.u64 %0, t; }" : "=r"(a) : "l"(p));
    return a;
}
#define CP_ASYNC16(dst, src) \
    asm volatile("cp.async.cg.shared.global [%0], [%1], 16;\n" :: "r"(dst), "l"(src))
#define CP_COMMIT() asm volatile("cp.async.commit_group;\n" ::: "memory")
#define CP_WAIT(n)  asm volatile("cp.async.wait_group %0;\n" :: "n"(n) : "memory")

__device__ __forceinline__ void split2h(float x, __half& a, __half& b) {
    a = __float2half_rn(x); float r = x - __half2float(a);
    b = __float2half_rn(r);
}

__device__ __forceinline__ void mma_f16(float* c, const uint32_t* a, const uint32_t* b) {
    asm volatile("mma.sync.aligned.m16n8k16.row.col.f32.f16.f16.f32 "
        "{%0,%1,%2,%3}, {%4,%5,%6,%7}, {%8,%9}, {%0,%1,%2,%3};"
        : "+f"(c[0]), "+f"(c[1]), "+f"(c[2]), "+f"(c[3])
        : "r"(a[0]), "r"(a[1]), "r"(a[2]), "r"(a[3]), "r"(b[0]), "r"(b[1]));
}

// ---------------- prep kernels -----------------------------------------------
__global__ void prep_aff(const float* __restrict__ bn_q, const float* __restrict__ bn_k,
                         const float* __restrict__ bn_v, const float* __restrict__ b_proj,
                         const float* __restrict__ bn_proj, const float* __restrict__ b_fc1,
                         const float* __restrict__ bn_fc1, const float* __restrict__ b_fc2,
                         const float* __restrict__ bn_fc2)
{
    for (int i = threadIdx.x; i < ATOT; i += blockDim.x) {
        const float* bn; const float* bias = 0; int Cn, ch;
        if (i < 256)       { bn = bn_q;    Cn = 256;  ch = i; }
        else if (i < 512)  { bn = bn_k;    Cn = 256;  ch = i - 256; }
        else if (i < 768)  { bn = bn_v;    Cn = 256;  ch = i - 512; }
        else if (i < 1024) { bn = bn_proj; Cn = 256;  ch = i - 768;  bias = b_proj; }
        else if (i < 2048) { bn = bn_fc1;  Cn = 1024; ch = i - 1024; bias = b_fc1; }
        else               { bn = bn_fc2;  Cn = 256;  ch = i - 2048; bias = b_fc2; }
        float g = bn[0*Cn+ch], be = bn[1*Cn+ch], m = bn[2*Cn+ch], va = bn[3*Cn+ch];
        float rs = (float)(1.0 / sqrt((double)va + 1e-5));
        g_alpha[i] = g * rs;
        g_off[i]   = (bias ? bias[ch] : 0.0f) - m;
        g_beta[i]  = be;
    }
}

__global__ void prep_w_real(const float* __restrict__ wq, const float* __restrict__ wk,
                            const float* __restrict__ wv, const float* __restrict__ wf1)
{
    int i = blockIdx.x * 256 + threadIdx.x;
    if (i >= WR_SZ) return;
    int row = i >> 8, k = i & 255;
    float w;
    if (row < 256)       w = wq[row*256 + k];
    else if (row < 512)  w = wk[(row-256)*256 + k];
    else if (row < 768)  w = wv[(row-512)*256 + k];
    else                 w = wf1[(row-768)*256 + k];
    split2h(w, g_wr[0][i], g_wr[1][i]);
}

__global__ void prep_w_bin(const float* __restrict__ wp, const float* __restrict__ wf2)
{
    int i = blockIdx.x * 256 + threadIdx.x;
    if (i >= 65536 + 262144) return;
    if (i < 65536) split2h(wp[i], g_wpb[0][i], g_wpb[1][i]);
    else { int j = i - 65536; split2h(wf2[j], g_wf2b[0][j], g_wf2b[1][j]); }
}

// x [tb][c][n] -> g_xt [tb][n][c] fp32 + fp16 2-split
__global__ void transpose_split(const float* __restrict__ x)
{
    __shared__ float tile[32][33];
    int c0 = blockIdx.x * 32, n0 = blockIdx.y * 32, tb = blockIdx.z;
    int tx = threadIdx.x & 31, ty = threadIdx.x >> 5;
    const float* xb = x + (size_t)tb * C_ * N_;
    #pragma unroll
    for (int j = 0; j < 4; j++)
        tile[ty + 8*j][tx] = xb[(size_t)(c0 + ty + 8*j) * N_ + n0 + tx];
    __syncthreads();
    #pragma unroll
    for (int j = 0; j < 4; j++) {
        int n = n0 + ty + 8*j, c = c0 + tx;
        float v = tile[tx][ty + 8*j];
        size_t idx = ((size_t)tb * N_ + n) * C_ + c;
        g_xt[idx] = v;
        split2h(v, g_xsp[0][idx], g_xsp[1][idx]);
    }
}

// ---------------- mma.sync fp16 split-GEMM (R7-proven) ------------------------
// Y[tb][n][m] = alpha[m]*( sum_k W[m,k]*Act[tb,n,k] + off[m] ) + beta[m]
// Block: 128n x 128m, 8 warps (2n x 4m), warp tile 64n x 32m.
// NT=3 (real input): (w1,x0),(w0,x1),(w0,x0). NT=2 (binary): (w1,s),(w0,s).
template<int KTOT, int NT>
__global__ __launch_bounds__(256)
void gemm_mma(const __half* __restrict__ Act, size_t actStride,
              const __half* __restrict__ Wt, size_t wStride,
              float* __restrict__ Y, int Mtot,
              const float* __restrict__ alpha, const float* __restrict__ offv,
              const float* __restrict__ beta)
{
    constexpr int KC   = KTOT / 32;
    constexpr int NSEG = NT * KC;
    constexpr int PITCH  = 80;
    constexpr int TILEB  = 128 * PITCH;     // 10240
    constexpr int STAGEB = 2 * TILEB;       // 20480

    extern __shared__ char smem[];
    const uint32_t sb = smem_u32(smem);
    const int tid  = threadIdx.x;
    const int lane = tid & 31, warp = tid >> 5;
    const int wn = warp & 1, wm = warp >> 1;
    const int n0 = blockIdx.x * 128, m0 = blockIdx.y * 128;
    const int tbz = blockIdx.z;

    const int WA3[3] = {1,0,0};
    const int XB3[3] = {0,1,0};
    const int WA2[2] = {1,0};
    const int XB2[2] = {0,0};

    const int r_ = tid >> 2, c_ = tid & 3;

    auto load = [&](int seg, int st) {
        if (seg < NSEG) {
            int term = seg / KC, kc = seg - term * KC;
            int wa = (NT == 3) ? WA3[term] : WA2[term];
            int xb = (NT == 3) ? XB3[term] : XB2[term];
            const __half* ap = Act + (size_t)xb * actStride
                          + ((size_t)tbz * N_ + n0) * KTOT + kc * 32;
            const __half* wp = Wt + (size_t)wa * wStride + (size_t)m0 * KTOT + kc * 32;
            uint32_t ab = sb + st * STAGEB, bbs = ab + TILEB;
            #pragma unroll
            for (int j = 0; j < 2; j++) {
                int r = r_ + j * 64;
                CP_ASYNC16(ab  + r * PITCH + c_ * 16, ap + (size_t)r * KTOT + c_ * 8);
                CP_ASYNC16(bbs + r * PITCH + c_ * 16, wp + (size_t)r * KTOT + c_ * 8);
            }
        }
        CP_COMMIT();
    };

    float acc[4][4][4];
    #pragma unroll
    for (int i = 0; i < 4; i++)
        #pragma unroll
        for (int j = 0; j < 4; j++)
            #pragma unroll
            for (int v = 0; v < 4; v++) acc[i][j][v] = 0.0f;

    load(0, 0);
    load(1, 1);

    for (int seg = 0; seg < NSEG; ++seg) {
        CP_WAIT(1);
        __syncthreads();
        load(seg + 2, (seg + 2) % 3);

        uint32_t ab = sb + (seg % 3) * STAGEB, bbs = ab + TILEB;
        #pragma unroll
        for (int ki = 0; ki < 2; ki++) {
            uint32_t a[4][4];
            #pragma unroll
            for (int ni = 0; ni < 4; ni++) {
                int row = wn * 64 + ni * 16 + (lane & 15);
                int cc  = ki * 2 + (lane >> 4);
                uint32_t ad = ab + row * PITCH + cc * 16;
                asm volatile("ldmatrix.sync.aligned.m8n8.x4.shared.b16 {%0,%1,%2,%3}, [%4];"
                    : "=r"(a[ni][0]), "=r"(a[ni][1]), "=r"(a[ni][2]), "=r"(a[ni][3])
                    : "r"(ad));
            }
            uint32_t b[4][2];
            #pragma unroll
            for (int mi2 = 0; mi2 < 2; mi2++) {
                int row = wm * 32 + mi2 * 16 + (lane & 7) + ((lane >> 4) << 3);
                int cc  = ki * 2 + ((lane >> 3) & 1);
                uint32_t bd = bbs + row * PITCH + cc * 16;
                uint32_t r0, r1, r2, r3;
                asm volatile("ldmatrix.sync.aligned.m8n8.x4.shared.b16 {%0,%1,%2,%3}, [%4];"
                    : "=r"(r0), "=r"(r1), "=r"(r2), "=r"(r3) : "r"(bd));
                b[mi2*2+0][0] = r0; b[mi2*2+0][1] = r1;
                b[mi2*2+1][0] = r2; b[mi2*2+1][1] = r3;
            }
            #pragma unroll
            for (int ni = 0; ni < 4; ni++)
                #pragma unroll
                for (int mi = 0; mi < 4; mi++)
                    mma_f16(acc[ni][mi], a[ni], b[mi]);
        }
    }

    // epilogue: BN affine + store [n][m] (float2, 32B-sector coalesced)
    const int group = lane >> 2, tig = lane & 3;
    #pragma unroll
    for (int mi = 0; mi < 4; mi++) {
        int m = m0 + wm * 32 + mi * 8 + tig * 2;
        float2 al = *(const float2*)&alpha[m];
        float2 of = *(const float2*)&offv[m];
        float2 be = *(const float2*)&beta[m];
        #pragma unroll
        for (int ni = 0; ni < 4; ni++)
            #pragma unroll
            for (int v = 0; v < 2; v++) {
                int n = n0 + wn * 64 + ni * 16 + group + v * 8;
                float2 val;
                val.x = al.x * (acc[ni][mi][v*2+0] + of.x) + be.x;
                val.y = al.y * (acc[ni][mi][v*2+1] + of.y) + be.y;
                *(float2*)&Y[((size_t)tbz * N_ + n) * Mtot + m] = val;
            }
    }
}

// ---------------- LIF kernels ------------------------------------------------
__global__ void lif_to_half(const float* __restrict__ y, __half* __restrict__ o,
                            size_t S, float vth)
{
    size_t i = (size_t)blockIdx.x * blockDim.x + threadIdx.x;
    if (i >= S) return;
    float v = 0.0f;
    #pragma unroll
    for (int t = 0; t < T_; t++) {
        size_t idx = (size_t)t * S + i;
        float xx = y[idx];
        v = v + (xx - v) * 0.5f;
        float s = (v >= vth) ? 1.0f : 0.0f;
        o[idx] = __float2half_rn(s);
        if (s != 0.0f) v = 0.0f;
    }
}
// x1 = xt + spike(p); write x1 and its fp16 2-split
__global__ void lif_add_split(const float* __restrict__ p, size_t S)
{
    size_t i = (size_t)blockIdx.x * blockDim.x + threadIdx.x;
    if (i >= S) return;
    float v = 0.0f;
    #pragma unroll
    for (int t = 0; t < T_; t++) {
        size_t idx = (size_t)t * S + i;
        float xx = p[idx];
        v = v + (xx - v) * 0.5f;
        float s = (v >= 1.0f) ? 1.0f : 0.0f;
        float x1 = g_xt[idx] + s;
        g_x1[idx] = x1;
        split2h(x1, g_ps[0][idx], g_ps[1][idx]);
        if (s != 0.0f) v = 0.0f;
    }
}
// out[t,b,c,n] = x1 + spike(y2); internal buffers are [tb][n][c]
__global__ void lif_final(float* __restrict__ out, size_t S)
{
    size_t i = (size_t)blockIdx.x * blockDim.x + threadIdx.x;
    if (i >= S) return;
    int b = (int)(i / ((size_t)N_ * C_));
    int r = (int)(i % ((size_t)N_ * C_));
    int n = r >> 8, c = r & 255;
    float v = 0.0f;
    #pragma unroll
    for (int t = 0; t < T_; t++) {
        size_t idx = (size_t)t * S + i;
        float xx = g_y2[idx];
        v = v + (xx - v) * 0.5f;
        float s = (v >= 1.0f) ? 1.0f : 0.0f;
        out[(((size_t)t * B_ + b) * C_ + c) * N_ + n] = g_x1[idx] + s;
        if (s != 0.0f) v = 0.0f;
    }
}

// ---------------- attention (exact integer-valued fp32; half spike inputs) ----
__global__ __launch_bounds__(256) void attn_kernel()
{
    int h  = blockIdx.x & 7;
    int tb = blockIdx.x >> 3;
    const __half* base = g_qkvh + (size_t)tb * N_ * 768;

    __shared__ float ks[128][33];
    __shared__ float vs[128][36];
    __shared__ float kvs[32][33];

    int tid = threadIdx.x;
    int d  = tid >> 3;
    int e4 = (tid & 7) * 4;
    float acc[4] = {0.f, 0.f, 0.f, 0.f};

    for (int n0 = 0; n0 < N_; n0 += 128) {
        for (int i = tid; i < 128 * 32; i += 256) {
            int nl = i >> 5, dd = i & 31;
            const __half* row = base + (size_t)(n0 + nl) * 768 + h * 32;
            ks[nl][dd] = __half2float(row[256 + dd]);
            vs[nl][dd] = __half2float(row[512 + dd]);
        }
        __syncthreads();
        for (int n = 0; n < 128; n++) {
            float kd = ks[n][d];
            float4 vv = *(const float4*)&vs[n][e4];
            acc[0] += kd * vv.x; acc[1] += kd * vv.y;
            acc[2] += kd * vv.z; acc[3] += kd * vv.w;
        }
        __syncthreads();
    }
    kvs[d][e4+0] = acc[0]; kvs[d][e4+1] = acc[1];
    kvs[d][e4+2] = acc[2]; kvs[d][e4+3] = acc[3];
    __syncthreads();

    for (int n = tid; n < N_; n += 256) {
        const __half* qrow = base + (size_t)n * 768 + h * 32;
        float a[32];
        #pragma unroll
        for (int e = 0; e < 32; e++) a[e] = 0.0f;
        #pragma unroll
        for (int dd = 0; dd < 32; dd++) {
            if (__half2float(qrow[dd]) != 0.0f) {
                #pragma unroll
                for (int e = 0; e < 32; e++) a[e] += kvs[dd][e];
            }
        }
        float* ao = g_a + ((size_t)tb * N_ + n) * C_ + h * 32;
        #pragma unroll
        for (int e = 0; e < 32; e += 4) {
            float4 w;
            w.x = a[e]*0.125f; w.y = a[e+1]*0.125f;
            w.z = a[e+2]*0.125f; w.w = a[e+3]*0.125f;
            *(float4*)(ao + e) = w;
        }
    }
}

// ---------------- launch -----------------------------------------------------
extern "C" void kernel_launch(void* const* d_in, const int* in_sizes, int n_in,
                              void* d_out, int out_size)
{
    const float* x       = (const float*)d_in[0];
    const float* wq      = (const float*)d_in[2];
    const float* bn_q    = (const float*)d_in[3];
    const float* wk      = (const float*)d_in[4];
    const float* bn_k    = (const float*)d_in[5];
    const float* wv      = (const float*)d_in[6];
    const float* bn_v    = (const float*)d_in[7];
    const float* w_proj  = (const float*)d_in[8];
    const float* b_proj  = (const float*)d_in[9];
    const float* bn_proj = (const float*)d_in[10];
    const float* w_fc1   = (const float*)d_in[11];
    const float* b_fc1   = (const float*)d_in[12];
    const float* bn_fc1  = (const float*)d_in[13];
    const float* w_fc2   = (const float*)d_in[14];
    const float* b_fc2   = (const float*)d_in[15];
    const float* bn_fc2  = (const float*)d_in[16];
    float* out = (float*)d_out;

    __half *wr, *xsp, *ps, *wpb, *wf2b, *ab, *h1b, *qkvh;
    float *qkv, *a, *p, *h1, *y2, *al, *of, *be;
    cudaGetSymbolAddress((void**)&wr,   g_wr);
    cudaGetSymbolAddress((void**)&wpb,  g_wpb);
    cudaGetSymbolAddress((void**)&wf2b, g_wf2b);
    cudaGetSymbolAddress((void**)&xsp,  g_xsp);
    cudaGetSymbolAddress((void**)&ps,   g_ps);
    cudaGetSymbolAddress((void**)&ab,   g_ab);
    cudaGetSymbolAddress((void**)&h1b,  g_h1b);
    cudaGetSymbolAddress((void**)&qkvh, g_qkvh);
    cudaGetSymbolAddress((void**)&qkv,  g_qkv);
    cudaGetSymbolAddress((void**)&a,    g_a);
    cudaGetSymbolAddress((void**)&p,    g_p);
    cudaGetSymbolAddress((void**)&h1,   g_h1);
    cudaGetSymbolAddress((void**)&y2,   g_y2);
    cudaGetSymbolAddress((void**)&al,   g_alpha);
    cudaGetSymbolAddress((void**)&of,   g_off);
    cudaGetSymbolAddress((void**)&be,   g_beta);

    const int SMEM = 3 * 20480;   // 61440
    cudaFuncSetAttribute(gemm_mma<256,3>,
                         cudaFuncAttributeMaxDynamicSharedMemorySize, SMEM);
    cudaFuncSetAttribute(gemm_mma<256,2>,
                         cudaFuncAttributeMaxDynamicSharedMemorySize, SMEM);
    cudaFuncSetAttribute(gemm_mma<1024,2>,
                         cudaFuncAttributeMaxDynamicSharedMemorySize, SMEM);

    prep_aff<<<1, 256>>>(bn_q, bn_k, bn_v, b_proj, bn_proj, b_fc1, bn_fc1, b_fc2, bn_fc2);
    prep_w_real<<<(WR_SZ + 255)/256, 256>>>(wq, wk, wv, w_fc1);
    prep_w_bin<<<(65536 + 262144 + 255)/256, 256>>>(w_proj, w_fc2);
    transpose_split<<<dim3(8, 32, TB_), 256>>>(x);

    // qkv: M=768, fp16 3-term (real input) -> fp32 preact
    gemm_mma<256,3><<<dim3(8, 6, TB_), 256, SMEM>>>(
        xsp, TCN, wr, WR_SZ, qkv, 768, al + AOFF_QKV, of + AOFF_QKV, be + AOFF_QKV);
    // LIF -> fp16 spikes (half traffic vs in-place fp32)
    lif_to_half<<<(int)(S_QKV/256), 256>>>(qkv, qkvh, S_QKV, 1.0f);

    attn_kernel<<<TB_ * HEADS_, 256>>>();
    lif_to_half<<<(int)(S_C/256), 256>>>(a, ab, S_C, 0.5f);

    // proj: M=256, fp16 2-term (binary input)
    gemm_mma<256,2><<<dim3(8, 2, TB_), 256, SMEM>>>(
        ab, 0, wpb, 65536, p, 256, al + AOFF_P, of + AOFF_P, be + AOFF_P);
    lif_add_split<<<(int)(S_C/256), 256>>>(p, S_C);

    // fc1: M=1024, fp16 3-term (real input), weights at rows 768..1791
    gemm_mma<256,3><<<dim3(8, 8, TB_), 256, SMEM>>>(
        ps, TCN, wr + 768*256, WR_SZ, h1, 1024, al + AOFF_F1, of + AOFF_F1, be + AOFF_F1);
    lif_to_half<<<(int)(S_H/256), 256>>>(h1, h1b, S_H, 1.0f);

    // fc2: M=256, K=1024, fp16 2-term (binary input)
    gemm_mma<1024,2><<<dim3(8, 2, TB_), 256, SMEM>>>(
        h1b, 0, wf2b, 262144, y2, 256, al + AOFF_F2, of + AOFF_F2, be + AOFF_F2);
    lif_final<<<(int)(S_C/256), 256>>>(out, S_C);
}

// round 10
// speedup vs baseline: 1.2774x; 1.0723x over previous
#include <cuda_runtime.h>
#include <cuda_fp16.h>
#include <math.h>
#include <stdint.h>

// ---------------- shapes -----------------------------------------------------
#define T_ 4
#define B_ 16
#define C_ 256
#define N_ 1024
#define HD_ 1024
#define HEADS_ 8
#define TB_ (T_*B_)

#define S_C   ((size_t)B_*N_*C_)        // 4,194,304
#define S_QKV ((size_t)B_*N_*768)       // 12,582,912
#define S_H   ((size_t)B_*N_*HD_)       // 16,777,216
#define TCN   ((size_t)T_*S_C)
#define TQKV  ((size_t)T_*S_QKV)
#define THN   ((size_t)T_*S_H)

#define WR_ROWS 1792
#define WR_SZ   (WR_ROWS*256)           // 458752
#define AOFF_QKV  0
#define AOFF_P    768
#define AOFF_F1   1024
#define AOFF_F2   2048
#define ATOT      2304

// ---------------- device scratch ---------------------------------------------
__device__ __half g_wr  [2][WR_SZ];     // fp16 2-split (qkv + fc1 weights)
__device__ __half g_wpb [2][65536];     // fp16 2-split proj weights
__device__ __half g_wf2b[2][262144];    // fp16 2-split fc2 weights
__device__ float g_alpha[ATOT], g_off[ATOT], g_beta[ATOT];

__device__ float  g_xt  [TCN];          // x [tb][n][c] fp32
__device__ __half g_xsp [2][TCN];       // x fp16 2-split
__device__ float  g_qkv [TQKV];         // qkv preact fp32
__device__ __half g_qkvh[TQKV];         // qkv spikes fp16
__device__ float  g_a   [TCN];          // attn values
__device__ __half g_ab  [TCN];          // attn spikes fp16
__device__ float  g_p   [TCN];          // proj preact
__device__ float  g_x1  [TCN];          // x + attn spikes
__device__ __half g_ps  [2][TCN];       // x1 fp16 2-split
__device__ float  g_h1  [THN];          // fc1 preact
__device__ __half g_h1b [THN];          // fc1 spikes fp16
__device__ float  g_y2  [TCN];          // fc2 preact

// ---------------- helpers ----------------------------------------------------
__device__ __forceinline__ uint32_t smem_u32(const void* p) {
    uint32_t a;
    asm("{ .reg .u64 t; cvta.to.shared.u64 t, %1; cvt.u32.u64 %0, t; }" : "=r"(a) : "l"(p));
    return a;
}
#define CP_ASYNC16(dst, src) \
    asm volatile("cp.async.cg.shared.global [%0], [%1], 16;\n" :: "r"(dst), "l"(src))
#define CP_COMMIT() asm volatile("cp.async.commit_group;\n" ::: "memory")
#define CP_WAIT(n)  asm volatile("cp.async.wait_group %0;\n" :: "n"(n) : "memory")

__device__ __forceinline__ void split2h(float x, __half& a, __half& b) {
    a = __float2half_rn(x); float r = x - __half2float(a);
    b = __float2half_rn(r);
}

__device__ __forceinline__ void mma_f16(float* c, const uint32_t* a, const uint32_t* b) {
    asm volatile("mma.sync.aligned.m16n8k16.row.col.f32.f16.f16.f32 "
        "{%0,%1,%2,%3}, {%4,%5,%6,%7}, {%8,%9}, {%0,%1,%2,%3};"
        : "+f"(c[0]), "+f"(c[1]), "+f"(c[2]), "+f"(c[3])
        : "r"(a[0]), "r"(a[1]), "r"(a[2]), "r"(a[3]), "r"(b[0]), "r"(b[1]));
}

__device__ __forceinline__ uint32_t h2u(__half2 h) {
    return *reinterpret_cast<uint32_t*>(&h);
}

// ---------------- prep kernels -----------------------------------------------
__global__ void prep_aff(const float* __restrict__ bn_q, const float* __restrict__ bn_k,
                         const float* __restrict__ bn_v, const float* __restrict__ b_proj,
                         const float* __restrict__ bn_proj, const float* __restrict__ b_fc1,
                         const float* __restrict__ bn_fc1, const float* __restrict__ b_fc2,
                         const float* __restrict__ bn_fc2)
{
    for (int i = threadIdx.x; i < ATOT; i += blockDim.x) {
        const float* bn; const float* bias = 0; int Cn, ch;
        if (i < 256)       { bn = bn_q;    Cn = 256;  ch = i; }
        else if (i < 512)  { bn = bn_k;    Cn = 256;  ch = i - 256; }
        else if (i < 768)  { bn = bn_v;    Cn = 256;  ch = i - 512; }
        else if (i < 1024) { bn = bn_proj; Cn = 256;  ch = i - 768;  bias = b_proj; }
        else if (i < 2048) { bn = bn_fc1;  Cn = 1024; ch = i - 1024; bias = b_fc1; }
        else               { bn = bn_fc2;  Cn = 256;  ch = i - 2048; bias = b_fc2; }
        float g = bn[0*Cn+ch], be = bn[1*Cn+ch], m = bn[2*Cn+ch], va = bn[3*Cn+ch];
        float rs = (float)(1.0 / sqrt((double)va + 1e-5));
        g_alpha[i] = g * rs;
        g_off[i]   = (bias ? bias[ch] : 0.0f) - m;
        g_beta[i]  = be;
    }
}

__global__ void prep_w_real(const float* __restrict__ wq, const float* __restrict__ wk,
                            const float* __restrict__ wv, const float* __restrict__ wf1)
{
    int i = blockIdx.x * 256 + threadIdx.x;
    if (i >= WR_SZ) return;
    int row = i >> 8, k = i & 255;
    float w;
    if (row < 256)       w = wq[row*256 + k];
    else if (row < 512)  w = wk[(row-256)*256 + k];
    else if (row < 768)  w = wv[(row-512)*256 + k];
    else                 w = wf1[(row-768)*256 + k];
    split2h(w, g_wr[0][i], g_wr[1][i]);
}

__global__ void prep_w_bin(const float* __restrict__ wp, const float* __restrict__ wf2)
{
    int i = blockIdx.x * 256 + threadIdx.x;
    if (i >= 65536 + 262144) return;
    if (i < 65536) split2h(wp[i], g_wpb[0][i], g_wpb[1][i]);
    else { int j = i - 65536; split2h(wf2[j], g_wf2b[0][j], g_wf2b[1][j]); }
}

// x [tb][c][n] -> g_xt [tb][n][c] fp32 + fp16 2-split
__global__ void transpose_split(const float* __restrict__ x)
{
    __shared__ float tile[32][33];
    int c0 = blockIdx.x * 32, n0 = blockIdx.y * 32, tb = blockIdx.z;
    int tx = threadIdx.x & 31, ty = threadIdx.x >> 5;
    const float* xb = x + (size_t)tb * C_ * N_;
    #pragma unroll
    for (int j = 0; j < 4; j++)
        tile[ty + 8*j][tx] = xb[(size_t)(c0 + ty + 8*j) * N_ + n0 + tx];
    __syncthreads();
    #pragma unroll
    for (int j = 0; j < 4; j++) {
        int n = n0 + ty + 8*j, c = c0 + tx;
        float v = tile[tx][ty + 8*j];
        size_t idx = ((size_t)tb * N_ + n) * C_ + c;
        g_xt[idx] = v;
        split2h(v, g_xsp[0][idx], g_xsp[1][idx]);
    }
}

// ---------------- mma.sync fp16 split-GEMM (R7-proven) ------------------------
template<int KTOT, int NT>
__global__ __launch_bounds__(256)
void gemm_mma(const __half* __restrict__ Act, size_t actStride,
              const __half* __restrict__ Wt, size_t wStride,
              float* __restrict__ Y, int Mtot,
              const float* __restrict__ alpha, const float* __restrict__ offv,
              const float* __restrict__ beta)
{
    constexpr int KC   = KTOT / 32;
    constexpr int NSEG = NT * KC;
    constexpr int PITCH  = 80;
    constexpr int TILEB  = 128 * PITCH;
    constexpr int STAGEB = 2 * TILEB;

    extern __shared__ char smem[];
    const uint32_t sb = smem_u32(smem);
    const int tid  = threadIdx.x;
    const int lane = tid & 31, warp = tid >> 5;
    const int wn = warp & 1, wm = warp >> 1;
    const int n0 = blockIdx.x * 128, m0 = blockIdx.y * 128;
    const int tbz = blockIdx.z;

    const int WA3[3] = {1,0,0};
    const int XB3[3] = {0,1,0};
    const int WA2[2] = {1,0};
    const int XB2[2] = {0,0};

    const int r_ = tid >> 2, c_ = tid & 3;

    auto load = [&](int seg, int st) {
        if (seg < NSEG) {
            int term = seg / KC, kc = seg - term * KC;
            int wa = (NT == 3) ? WA3[term] : WA2[term];
            int xb = (NT == 3) ? XB3[term] : XB2[term];
            const __half* ap = Act + (size_t)xb * actStride
                          + ((size_t)tbz * N_ + n0) * KTOT + kc * 32;
            const __half* wp = Wt + (size_t)wa * wStride + (size_t)m0 * KTOT + kc * 32;
            uint32_t ab = sb + st * STAGEB, bbs = ab + TILEB;
            #pragma unroll
            for (int j = 0; j < 2; j++) {
                int r = r_ + j * 64;
                CP_ASYNC16(ab  + r * PITCH + c_ * 16, ap + (size_t)r * KTOT + c_ * 8);
                CP_ASYNC16(bbs + r * PITCH + c_ * 16, wp + (size_t)r * KTOT + c_ * 8);
            }
        }
        CP_COMMIT();
    };

    float acc[4][4][4];
    #pragma unroll
    for (int i = 0; i < 4; i++)
        #pragma unroll
        for (int j = 0; j < 4; j++)
            #pragma unroll
            for (int v = 0; v < 4; v++) acc[i][j][v] = 0.0f;

    load(0, 0);
    load(1, 1);

    for (int seg = 0; seg < NSEG; ++seg) {
        CP_WAIT(1);
        __syncthreads();
        load(seg + 2, (seg + 2) % 3);

        uint32_t ab = sb + (seg % 3) * STAGEB, bbs = ab + TILEB;
        #pragma unroll
        for (int ki = 0; ki < 2; ki++) {
            uint32_t a[4][4];
            #pragma unroll
            for (int ni = 0; ni < 4; ni++) {
                int row = wn * 64 + ni * 16 + (lane & 15);
                int cc  = ki * 2 + (lane >> 4);
                uint32_t ad = ab + row * PITCH + cc * 16;
                asm volatile("ldmatrix.sync.aligned.m8n8.x4.shared.b16 {%0,%1,%2,%3}, [%4];"
                    : "=r"(a[ni][0]), "=r"(a[ni][1]), "=r"(a[ni][2]), "=r"(a[ni][3])
                    : "r"(ad));
            }
            uint32_t b[4][2];
            #pragma unroll
            for (int mi2 = 0; mi2 < 2; mi2++) {
                int row = wm * 32 + mi2 * 16 + (lane & 7) + ((lane >> 4) << 3);
                int cc  = ki * 2 + ((lane >> 3) & 1);
                uint32_t bd = bbs + row * PITCH + cc * 16;
                uint32_t r0, r1, r2, r3;
                asm volatile("ldmatrix.sync.aligned.m8n8.x4.shared.b16 {%0,%1,%2,%3}, [%4];"
                    : "=r"(r0), "=r"(r1), "=r"(r2), "=r"(r3) : "r"(bd));
                b[mi2*2+0][0] = r0; b[mi2*2+0][1] = r1;
                b[mi2*2+1][0] = r2; b[mi2*2+1][1] = r3;
            }
            #pragma unroll
            for (int ni = 0; ni < 4; ni++)
                #pragma unroll
                for (int mi = 0; mi < 4; mi++)
                    mma_f16(acc[ni][mi], a[ni], b[mi]);
        }
    }

    const int group = lane >> 2, tig = lane & 3;
    #pragma unroll
    for (int mi = 0; mi < 4; mi++) {
        int m = m0 + wm * 32 + mi * 8 + tig * 2;
        float2 al = *(const float2*)&alpha[m];
        float2 of = *(const float2*)&offv[m];
        float2 be = *(const float2*)&beta[m];
        #pragma unroll
        for (int ni = 0; ni < 4; ni++)
            #pragma unroll
            for (int v = 0; v < 2; v++) {
                int n = n0 + wn * 64 + ni * 16 + group + v * 8;
                float2 val;
                val.x = al.x * (acc[ni][mi][v*2+0] + of.x) + be.x;
                val.y = al.y * (acc[ni][mi][v*2+1] + of.y) + be.y;
                *(float2*)&Y[((size_t)tbz * N_ + n) * Mtot + m] = val;
            }
    }
}

// ---------------- LIF kernels (vectorized x4) ---------------------------------
__global__ void lif_to_half4(const float* __restrict__ y, __half* __restrict__ o,
                             size_t S, float vth)
{
    size_t base = ((size_t)blockIdx.x * blockDim.x + threadIdx.x) * 4;
    if (base >= S) return;
    float v0 = 0.f, v1 = 0.f, v2 = 0.f, v3 = 0.f;
    #pragma unroll
    for (int t = 0; t < T_; t++) {
        size_t idx = (size_t)t * S + base;
        float4 xx = *(const float4*)&y[idx];
        v0 = v0 + (xx.x - v0) * 0.5f;
        v1 = v1 + (xx.y - v1) * 0.5f;
        v2 = v2 + (xx.z - v2) * 0.5f;
        v3 = v3 + (xx.w - v3) * 0.5f;
        float s0 = (v0 >= vth) ? 1.f : 0.f;
        float s1 = (v1 >= vth) ? 1.f : 0.f;
        float s2 = (v2 >= vth) ? 1.f : 0.f;
        float s3 = (v3 >= vth) ? 1.f : 0.f;
        if (s0 != 0.f) v0 = 0.f;
        if (s1 != 0.f) v1 = 0.f;
        if (s2 != 0.f) v2 = 0.f;
        if (s3 != 0.f) v3 = 0.f;
        uint2 pk = make_uint2(h2u(__floats2half2_rn(s0, s1)),
                              h2u(__floats2half2_rn(s2, s3)));
        *(uint2*)&o[idx] = pk;
    }
}

// x1 = xt + spike(p); write x1 and its fp16 2-split (vectorized x4)
__global__ void lif_add_split4(const float* __restrict__ p, size_t S)
{
    size_t base = ((size_t)blockIdx.x * blockDim.x + threadIdx.x) * 4;
    if (base >= S) return;
    float v0 = 0.f, v1 = 0.f, v2 = 0.f, v3 = 0.f;
    #pragma unroll
    for (int t = 0; t < T_; t++) {
        size_t idx = (size_t)t * S + base;
        float4 pp = *(const float4*)&p[idx];
        float4 xx = *(const float4*)&g_xt[idx];
        v0 = v0 + (pp.x - v0) * 0.5f;
        v1 = v1 + (pp.y - v1) * 0.5f;
        v2 = v2 + (pp.z - v2) * 0.5f;
        v3 = v3 + (pp.w - v3) * 0.5f;
        float s0 = (v0 >= 1.f) ? 1.f : 0.f;
        float s1 = (v1 >= 1.f) ? 1.f : 0.f;
        float s2 = (v2 >= 1.f) ? 1.f : 0.f;
        float s3 = (v3 >= 1.f) ? 1.f : 0.f;
        if (s0 != 0.f) v0 = 0.f;
        if (s1 != 0.f) v1 = 0.f;
        if (s2 != 0.f) v2 = 0.f;
        if (s3 != 0.f) v3 = 0.f;
        float4 X = make_float4(xx.x + s0, xx.y + s1, xx.z + s2, xx.w + s3);
        *(float4*)&g_x1[idx] = X;
        __half a0, b0, a1, b1, a2, b2, a3, b3;
        split2h(X.x, a0, b0); split2h(X.y, a1, b1);
        split2h(X.z, a2, b2); split2h(X.w, a3, b3);
        *(uint2*)&g_ps[0][idx] = make_uint2(h2u(__halves2half2(a0, a1)),
                                            h2u(__halves2half2(a2, a3)));
        *(uint2*)&g_ps[1][idx] = make_uint2(h2u(__halves2half2(b0, b1)),
                                            h2u(__halves2half2(b2, b3)));
    }
}

// out[t,b,c,n] = x1 + spike(y2); coalesced via 32x32 smem transpose tile.
// grid (C/32, N/32, B); thread owns 4 (n,c) elems, membrane state in regs.
__global__ void lif_final_t(float* __restrict__ out)
{
    __shared__ float st[32][33];     // [c-local][n-local]
    int c0 = blockIdx.x * 32, n0 = blockIdx.y * 32, b = blockIdx.z;
    int tx = threadIdx.x & 31, ty = threadIdx.x >> 5;
    float v[4] = {0.f, 0.f, 0.f, 0.f};
    for (int t = 0; t < T_; t++) {
        int tb = t * B_ + b;
        #pragma unroll
        for (int j = 0; j < 4; j++) {
            int n = n0 + ty + 8*j;
            size_t idx = ((size_t)tb * N_ + n) * C_ + c0 + tx;
            float y = g_y2[idx];
            v[j] = v[j] + (y - v[j]) * 0.5f;
            float s = (v[j] >= 1.f) ? 1.f : 0.f;
            if (s != 0.f) v[j] = 0.f;
            st[tx][ty + 8*j] = g_x1[idx] + s;
        }
        __syncthreads();
        #pragma unroll
        for (int j = 0; j < 4; j++) {
            int c = c0 + ty + 8*j;
            out[(((size_t)t * B_ + b) * C_ + c) * N_ + n0 + tx] = st[ty + 8*j][tx];
        }
        __syncthreads();
    }
}

// ---------------- attention (exact integer-valued fp32; half spike inputs) ----
__global__ __launch_bounds__(256) void attn_kernel()
{
    int h  = blockIdx.x & 7;
    int tb = blockIdx.x >> 3;
    const __half* base = g_qkvh + (size_t)tb * N_ * 768;

    __shared__ float ks[128][33];
    __shared__ float vs[128][36];
    __shared__ float kvs[32][33];

    int tid = threadIdx.x;
    int d  = tid >> 3;
    int e4 = (tid & 7) * 4;
    float acc[4] = {0.f, 0.f, 0.f, 0.f};

    for (int n0 = 0; n0 < N_; n0 += 128) {
        for (int i = tid; i < 128 * 32; i += 256) {
            int nl = i >> 5, dd = i & 31;
            const __half* row = base + (size_t)(n0 + nl) * 768 + h * 32;
            ks[nl][dd] = __half2float(row[256 + dd]);
            vs[nl][dd] = __half2float(row[512 + dd]);
        }
        __syncthreads();
        for (int n = 0; n < 128; n++) {
            float kd = ks[n][d];
            float4 vv = *(const float4*)&vs[n][e4];
            acc[0] += kd * vv.x; acc[1] += kd * vv.y;
            acc[2] += kd * vv.z; acc[3] += kd * vv.w;
        }
        __syncthreads();
    }
    kvs[d][e4+0] = acc[0]; kvs[d][e4+1] = acc[1];
    kvs[d][e4+2] = acc[2]; kvs[d][e4+3] = acc[3];
    __syncthreads();

    for (int n = tid; n < N_; n += 256) {
        const __half* qrow = base + (size_t)n * 768 + h * 32;
        float a[32];
        #pragma unroll
        for (int e = 0; e < 32; e++) a[e] = 0.0f;
        #pragma unroll
        for (int dd = 0; dd < 32; dd++) {
            if (__half2float(qrow[dd]) != 0.0f) {
                #pragma unroll
                for (int e = 0; e < 32; e++) a[e] += kvs[dd][e];
            }
        }
        float* ao = g_a + ((size_t)tb * N_ + n) * C_ + h * 32;
        #pragma unroll
        for (int e = 0; e < 32; e += 4) {
            float4 w;
            w.x = a[e]*0.125f; w.y = a[e+1]*0.125f;
            w.z = a[e+2]*0.125f; w.w = a[e+3]*0.125f;
            *(float4*)(ao + e) = w;
        }
    }
}

// ---------------- launch -----------------------------------------------------
extern "C" void kernel_launch(void* const* d_in, const int* in_sizes, int n_in,
                              void* d_out, int out_size)
{
    const float* x       = (const float*)d_in[0];
    const float* wq      = (const float*)d_in[2];
    const float* bn_q    = (const float*)d_in[3];
    const float* wk      = (const float*)d_in[4];
    const float* bn_k    = (const float*)d_in[5];
    const float* wv      = (const float*)d_in[6];
    const float* bn_v    = (const float*)d_in[7];
    const float* w_proj  = (const float*)d_in[8];
    const float* b_proj  = (const float*)d_in[9];
    const float* bn_proj = (const float*)d_in[10];
    const float* w_fc1   = (const float*)d_in[11];
    const float* b_fc1   = (const float*)d_in[12];
    const float* bn_fc1  = (const float*)d_in[13];
    const float* w_fc2   = (const float*)d_in[14];
    const float* b_fc2   = (const float*)d_in[15];
    const float* bn_fc2  = (const float*)d_in[16];
    float* out = (float*)d_out;

    __half *wr, *xsp, *ps, *wpb, *wf2b, *ab, *h1b, *qkvh;
    float *qkv, *a, *p, *h1, *y2, *al, *of, *be;
    cudaGetSymbolAddress((void**)&wr,   g_wr);
    cudaGetSymbolAddress((void**)&wpb,  g_wpb);
    cudaGetSymbolAddress((void**)&wf2b, g_wf2b);
    cudaGetSymbolAddress((void**)&xsp,  g_xsp);
    cudaGetSymbolAddress((void**)&ps,   g_ps);
    cudaGetSymbolAddress((void**)&ab,   g_ab);
    cudaGetSymbolAddress((void**)&h1b,  g_h1b);
    cudaGetSymbolAddress((void**)&qkvh, g_qkvh);
    cudaGetSymbolAddress((void**)&qkv,  g_qkv);
    cudaGetSymbolAddress((void**)&a,    g_a);
    cudaGetSymbolAddress((void**)&p,    g_p);
    cudaGetSymbolAddress((void**)&h1,   g_h1);
    cudaGetSymbolAddress((void**)&y2,   g_y2);
    cudaGetSymbolAddress((void**)&al,   g_alpha);
    cudaGetSymbolAddress((void**)&of,   g_off);
    cudaGetSymbolAddress((void**)&be,   g_beta);

    const int SMEM = 3 * 20480;   // 61440
    cudaFuncSetAttribute(gemm_mma<256,3>,
                         cudaFuncAttributeMaxDynamicSharedMemorySize, SMEM);
    cudaFuncSetAttribute(gemm_mma<256,2>,
                         cudaFuncAttributeMaxDynamicSharedMemorySize, SMEM);
    cudaFuncSetAttribute(gemm_mma<1024,2>,
                         cudaFuncAttributeMaxDynamicSharedMemorySize, SMEM);

    prep_aff<<<1, 256>>>(bn_q, bn_k, bn_v, b_proj, bn_proj, b_fc1, bn_fc1, b_fc2, bn_fc2);
    prep_w_real<<<(WR_SZ + 255)/256, 256>>>(wq, wk, wv, w_fc1);
    prep_w_bin<<<(65536 + 262144 + 255)/256, 256>>>(w_proj, w_fc2);
    transpose_split<<<dim3(8, 32, TB_), 256>>>(x);

    // qkv: M=768, fp16 3-term (real input) -> fp32 preact
    gemm_mma<256,3><<<dim3(8, 6, TB_), 256, SMEM>>>(
        xsp, TCN, wr, WR_SZ, qkv, 768, al + AOFF_QKV, of + AOFF_QKV, be + AOFF_QKV);
    lif_to_half4<<<(int)(S_QKV/4/256), 256>>>(qkv, qkvh, S_QKV, 1.0f);

    attn_kernel<<<TB_ * HEADS_, 256>>>();
    lif_to_half4<<<(int)(S_C/4/256), 256>>>(a, ab, S_C, 0.5f);

    // proj: M=256, fp16 2-term (binary input)
    gemm_mma<256,2><<<dim3(8, 2, TB_), 256, SMEM>>>(
        ab, 0, wpb, 65536, p, 256, al + AOFF_P, of + AOFF_P, be + AOFF_P);
    lif_add_split4<<<(int)(S_C/4/256), 256>>>(p, S_C);

    // fc1: M=1024, fp16 3-term (real input), weights at rows 768..1791
    gemm_mma<256,3><<<dim3(8, 8, TB_), 256, SMEM>>>(
        ps, TCN, wr + 768*256, WR_SZ, h1, 1024, al + AOFF_F1, of + AOFF_F1, be + AOFF_F1);
    lif_to_half4<<<(int)(S_H/4/256), 256>>>(h1, h1b, S_H, 1.0f);

    // fc2: M=256, K=1024, fp16 2-term (binary input)
    gemm_mma<1024,2><<<dim3(8, 2, TB_), 256, SMEM>>>(
        h1b, 0, wf2b, 262144, y2, 256, al + AOFF_F2, of + AOFF_F2, be + AOFF_F2);
    lif_final_t<<<dim3(C_/32, N_/32, B_), 256>>>(out);
}

// round 11
// speedup vs baseline: 1.4063x; 1.1009x over previous
#include <cuda_runtime.h>
#include <cuda_fp16.h>
#include <math.h>
#include <stdint.h>

// ---------------- shapes -----------------------------------------------------
#define T_ 4
#define B_ 16
#define C_ 256
#define N_ 1024
#define HD_ 1024
#define HEADS_ 8
#define TB_ (T_*B_)

#define S_C   ((size_t)B_*N_*C_)        // 4,194,304
#define S_QKV ((size_t)B_*N_*768)       // 12,582,912
#define S_H   ((size_t)B_*N_*HD_)       // 16,777,216
#define TCN   ((size_t)T_*S_C)
#define TQKV  ((size_t)T_*S_QKV)
#define THN   ((size_t)T_*S_H)

#define WR_ROWS 1792
#define WR_SZ   (WR_ROWS*256)           // 458752
#define AOFF_QKV  0
#define AOFF_P    768
#define AOFF_F1   1024
#define AOFF_F2   2048
#define ATOT      2304

// ---------------- device scratch ---------------------------------------------
__device__ __half g_wr  [2][WR_SZ];     // fp16 2-split (qkv + fc1 weights)
__device__ __half g_wpb [2][65536];     // fp16 2-split proj weights
__device__ __half g_wf2b[2][262144];    // fp16 2-split fc2 weights
__device__ float g_alpha[ATOT], g_off[ATOT], g_beta[ATOT];

__device__ float  g_xt  [TCN];          // x [tb][n][c] fp32
__device__ __half g_xsp [2][TCN];       // x fp16 2-split
__device__ float  g_qkv [TQKV];         // qkv preact fp32
__device__ __half g_qkvh[TQKV];         // qkv spikes fp16
__device__ float  g_kv  [TB_*HEADS_*32*32];  // kv matrices (2MB)
__device__ __half g_ab  [TCN];          // attn spikes fp16
__device__ float  g_p   [TCN];          // proj preact
__device__ __half g_ps  [2][TCN];       // x1 fp16 2-split (x1 = ps0+ps1)
__device__ float  g_h1  [THN];          // fc1 preact
__device__ __half g_h1b [THN];          // fc1 spikes fp16
__device__ float  g_y2  [TCN];          // fc2 preact

// ---------------- helpers ----------------------------------------------------
__device__ __forceinline__ uint32_t smem_u32(const void* p) {
    uint32_t a;
    asm("{ .reg .u64 t; cvta.to.shared.u64 t, %1; cvt.u32.u64 %0, t; }" : "=r"(a) : "l"(p));
    return a;
}
#define CP_ASYNC16(dst, src) \
    asm volatile("cp.async.cg.shared.global [%0], [%1], 16;\n" :: "r"(dst), "l"(src))
#define CP_COMMIT() asm volatile("cp.async.commit_group;\n" ::: "memory")
#define CP_WAIT(n)  asm volatile("cp.async.wait_group %0;\n" :: "n"(n) : "memory")

__device__ __forceinline__ void split2h(float x, __half& a, __half& b) {
    a = __float2half_rn(x); float r = x - __half2float(a);
    b = __float2half_rn(r);
}

__device__ __forceinline__ void mma_f16(float* c, const uint32_t* a, const uint32_t* b) {
    asm volatile("mma.sync.aligned.m16n8k16.row.col.f32.f16.f16.f32 "
        "{%0,%1,%2,%3}, {%4,%5,%6,%7}, {%8,%9}, {%0,%1,%2,%3};"
        : "+f"(c[0]), "+f"(c[1]), "+f"(c[2]), "+f"(c[3])
        : "r"(a[0]), "r"(a[1]), "r"(a[2]), "r"(a[3]), "r"(b[0]), "r"(b[1]));
}

__device__ __forceinline__ uint32_t h2u(__half2 h) {
    return *reinterpret_cast<uint32_t*>(&h);
}

// ---------------- prep kernels -----------------------------------------------
__global__ void prep_aff(const float* __restrict__ bn_q, const float* __restrict__ bn_k,
                         const float* __restrict__ bn_v, const float* __restrict__ b_proj,
                         const float* __restrict__ bn_proj, const float* __restrict__ b_fc1,
                         const float* __restrict__ bn_fc1, const float* __restrict__ b_fc2,
                         const float* __restrict__ bn_fc2)
{
    for (int i = threadIdx.x; i < ATOT; i += blockDim.x) {
        const float* bn; const float* bias = 0; int Cn, ch;
        if (i < 256)       { bn = bn_q;    Cn = 256;  ch = i; }
        else if (i < 512)  { bn = bn_k;    Cn = 256;  ch = i - 256; }
        else if (i < 768)  { bn = bn_v;    Cn = 256;  ch = i - 512; }
        else if (i < 1024) { bn = bn_proj; Cn = 256;  ch = i - 768;  bias = b_proj; }
        else if (i < 2048) { bn = bn_fc1;  Cn = 1024; ch = i - 1024; bias = b_fc1; }
        else               { bn = bn_fc2;  Cn = 256;  ch = i - 2048; bias = b_fc2; }
        float g = bn[0*Cn+ch], be = bn[1*Cn+ch], m = bn[2*Cn+ch], va = bn[3*Cn+ch];
        float rs = (float)(1.0 / sqrt((double)va + 1e-5));
        g_alpha[i] = g * rs;
        g_off[i]   = (bias ? bias[ch] : 0.0f) - m;
        g_beta[i]  = be;
    }
}

__global__ void prep_w_real(const float* __restrict__ wq, const float* __restrict__ wk,
                            const float* __restrict__ wv, const float* __restrict__ wf1)
{
    int i = blockIdx.x * 256 + threadIdx.x;
    if (i >= WR_SZ) return;
    int row = i >> 8, k = i & 255;
    float w;
    if (row < 256)       w = wq[row*256 + k];
    else if (row < 512)  w = wk[(row-256)*256 + k];
    else if (row < 768)  w = wv[(row-512)*256 + k];
    else                 w = wf1[(row-768)*256 + k];
    split2h(w, g_wr[0][i], g_wr[1][i]);
}

__global__ void prep_w_bin(const float* __restrict__ wp, const float* __restrict__ wf2)
{
    int i = blockIdx.x * 256 + threadIdx.x;
    if (i >= 65536 + 262144) return;
    if (i < 65536) split2h(wp[i], g_wpb[0][i], g_wpb[1][i]);
    else { int j = i - 65536; split2h(wf2[j], g_wf2b[0][j], g_wf2b[1][j]); }
}

// x [tb][c][n] -> g_xt [tb][n][c] fp32 + fp16 2-split
__global__ void transpose_split(const float* __restrict__ x)
{
    __shared__ float tile[32][33];
    int c0 = blockIdx.x * 32, n0 = blockIdx.y * 32, tb = blockIdx.z;
    int tx = threadIdx.x & 31, ty = threadIdx.x >> 5;
    const float* xb = x + (size_t)tb * C_ * N_;
    #pragma unroll
    for (int j = 0; j < 4; j++)
        tile[ty + 8*j][tx] = xb[(size_t)(c0 + ty + 8*j) * N_ + n0 + tx];
    __syncthreads();
    #pragma unroll
    for (int j = 0; j < 4; j++) {
        int n = n0 + ty + 8*j, c = c0 + tx;
        float v = tile[tx][ty + 8*j];
        size_t idx = ((size_t)tb * N_ + n) * C_ + c;
        g_xt[idx] = v;
        split2h(v, g_xsp[0][idx], g_xsp[1][idx]);
    }
}

// ---------------- mma.sync fp16 split-GEMM (R7-proven, unchanged) -------------
template<int KTOT, int NT>
__global__ __launch_bounds__(256)
void gemm_mma(const __half* __restrict__ Act, size_t actStride,
              const __half* __restrict__ Wt, size_t wStride,
              float* __restrict__ Y, int Mtot,
              const float* __restrict__ alpha, const float* __restrict__ offv,
              const float* __restrict__ beta)
{
    constexpr int KC   = KTOT / 32;
    constexpr int NSEG = NT * KC;
    constexpr int PITCH  = 80;
    constexpr int TILEB  = 128 * PITCH;
    constexpr int STAGEB = 2 * TILEB;

    extern __shared__ char smem[];
    const uint32_t sb = smem_u32(smem);
    const int tid  = threadIdx.x;
    const int lane = tid & 31, warp = tid >> 5;
    const int wn = warp & 1, wm = warp >> 1;
    const int n0 = blockIdx.x * 128, m0 = blockIdx.y * 128;
    const int tbz = blockIdx.z;

    const int WA3[3] = {1,0,0};
    const int XB3[3] = {0,1,0};
    const int WA2[2] = {1,0};
    const int XB2[2] = {0,0};

    const int r_ = tid >> 2, c_ = tid & 3;

    auto load = [&](int seg, int st) {
        if (seg < NSEG) {
            int term = seg / KC, kc = seg - term * KC;
            int wa = (NT == 3) ? WA3[term] : WA2[term];
            int xb = (NT == 3) ? XB3[term] : XB2[term];
            const __half* ap = Act + (size_t)xb * actStride
                          + ((size_t)tbz * N_ + n0) * KTOT + kc * 32;
            const __half* wp = Wt + (size_t)wa * wStride + (size_t)m0 * KTOT + kc * 32;
            uint32_t ab = sb + st * STAGEB, bbs = ab + TILEB;
            #pragma unroll
            for (int j = 0; j < 2; j++) {
                int r = r_ + j * 64;
                CP_ASYNC16(ab  + r * PITCH + c_ * 16, ap + (size_t)r * KTOT + c_ * 8);
                CP_ASYNC16(bbs + r * PITCH + c_ * 16, wp + (size_t)r * KTOT + c_ * 8);
            }
        }
        CP_COMMIT();
    };

    float acc[4][4][4];
    #pragma unroll
    for (int i = 0; i < 4; i++)
        #pragma unroll
        for (int j = 0; j < 4; j++)
            #pragma unroll
            for (int v = 0; v < 4; v++) acc[i][j][v] = 0.0f;

    load(0, 0);
    load(1, 1);

    for (int seg = 0; seg < NSEG; ++seg) {
        CP_WAIT(1);
        __syncthreads();
        load(seg + 2, (seg + 2) % 3);

        uint32_t ab = sb + (seg % 3) * STAGEB, bbs = ab + TILEB;
        #pragma unroll
        for (int ki = 0; ki < 2; ki++) {
            uint32_t a[4][4];
            #pragma unroll
            for (int ni = 0; ni < 4; ni++) {
                int row = wn * 64 + ni * 16 + (lane & 15);
                int cc  = ki * 2 + (lane >> 4);
                uint32_t ad = ab + row * PITCH + cc * 16;
                asm volatile("ldmatrix.sync.aligned.m8n8.x4.shared.b16 {%0,%1,%2,%3}, [%4];"
                    : "=r"(a[ni][0]), "=r"(a[ni][1]), "=r"(a[ni][2]), "=r"(a[ni][3])
                    : "r"(ad));
            }
            uint32_t b[4][2];
            #pragma unroll
            for (int mi2 = 0; mi2 < 2; mi2++) {
                int row = wm * 32 + mi2 * 16 + (lane & 7) + ((lane >> 4) << 3);
                int cc  = ki * 2 + ((lane >> 3) & 1);
                uint32_t bd = bbs + row * PITCH + cc * 16;
                uint32_t r0, r1, r2, r3;
                asm volatile("ldmatrix.sync.aligned.m8n8.x4.shared.b16 {%0,%1,%2,%3}, [%4];"
                    : "=r"(r0), "=r"(r1), "=r"(r2), "=r"(r3) : "r"(bd));
                b[mi2*2+0][0] = r0; b[mi2*2+0][1] = r1;
                b[mi2*2+1][0] = r2; b[mi2*2+1][1] = r3;
            }
            #pragma unroll
            for (int ni = 0; ni < 4; ni++)
                #pragma unroll
                for (int mi = 0; mi < 4; mi++)
                    mma_f16(acc[ni][mi], a[ni], b[mi]);
        }
    }

    const int group = lane >> 2, tig = lane & 3;
    #pragma unroll
    for (int mi = 0; mi < 4; mi++) {
        int m = m0 + wm * 32 + mi * 8 + tig * 2;
        float2 al = *(const float2*)&alpha[m];
        float2 of = *(const float2*)&offv[m];
        float2 be = *(const float2*)&beta[m];
        #pragma unroll
        for (int ni = 0; ni < 4; ni++)
            #pragma unroll
            for (int v = 0; v < 2; v++) {
                int n = n0 + wn * 64 + ni * 16 + group + v * 8;
                float2 val;
                val.x = al.x * (acc[ni][mi][v*2+0] + of.x) + be.x;
                val.y = al.y * (acc[ni][mi][v*2+1] + of.y) + be.y;
                *(float2*)&Y[((size_t)tbz * N_ + n) * Mtot + m] = val;
            }
    }
}

// ---------------- LIF kernels (vectorized x4) ---------------------------------
__global__ void lif_to_half4(const float* __restrict__ y, __half* __restrict__ o,
                             size_t S, float vth)
{
    size_t base = ((size_t)blockIdx.x * blockDim.x + threadIdx.x) * 4;
    if (base >= S) return;
    float v0 = 0.f, v1 = 0.f, v2 = 0.f, v3 = 0.f;
    #pragma unroll
    for (int t = 0; t < T_; t++) {
        size_t idx = (size_t)t * S + base;
        float4 xx = *(const float4*)&y[idx];
        v0 = v0 + (xx.x - v0) * 0.5f;
        v1 = v1 + (xx.y - v1) * 0.5f;
        v2 = v2 + (xx.z - v2) * 0.5f;
        v3 = v3 + (xx.w - v3) * 0.5f;
        float s0 = (v0 >= vth) ? 1.f : 0.f;
        float s1 = (v1 >= vth) ? 1.f : 0.f;
        float s2 = (v2 >= vth) ? 1.f : 0.f;
        float s3 = (v3 >= vth) ? 1.f : 0.f;
        if (s0 != 0.f) v0 = 0.f;
        if (s1 != 0.f) v1 = 0.f;
        if (s2 != 0.f) v2 = 0.f;
        if (s3 != 0.f) v3 = 0.f;
        uint2 pk = make_uint2(h2u(__floats2half2_rn(s0, s1)),
                              h2u(__floats2half2_rn(s2, s3)));
        *(uint2*)&o[idx] = pk;
    }
}

// x1 = xt + spike(p); write fp16 2-split only (x1 reconstructed later)
__global__ void lif_add_split4(const float* __restrict__ p, size_t S)
{
    size_t base = ((size_t)blockIdx.x * blockDim.x + threadIdx.x) * 4;
    if (base >= S) return;
    float v0 = 0.f, v1 = 0.f, v2 = 0.f, v3 = 0.f;
    #pragma unroll
    for (int t = 0; t < T_; t++) {
        size_t idx = (size_t)t * S + base;
        float4 pp = *(const float4*)&p[idx];
        float4 xx = *(const float4*)&g_xt[idx];
        v0 = v0 + (pp.x - v0) * 0.5f;
        v1 = v1 + (pp.y - v1) * 0.5f;
        v2 = v2 + (pp.z - v2) * 0.5f;
        v3 = v3 + (pp.w - v3) * 0.5f;
        float s0 = (v0 >= 1.f) ? 1.f : 0.f;
        float s1 = (v1 >= 1.f) ? 1.f : 0.f;
        float s2 = (v2 >= 1.f) ? 1.f : 0.f;
        float s3 = (v3 >= 1.f) ? 1.f : 0.f;
        if (s0 != 0.f) v0 = 0.f;
        if (s1 != 0.f) v1 = 0.f;
        if (s2 != 0.f) v2 = 0.f;
        if (s3 != 0.f) v3 = 0.f;
        float4 X = make_float4(xx.x + s0, xx.y + s1, xx.z + s2, xx.w + s3);
        __half a0, b0, a1, b1, a2, b2, a3, b3;
        split2h(X.x, a0, b0); split2h(X.y, a1, b1);
        split2h(X.z, a2, b2); split2h(X.w, a3, b3);
        *(uint2*)&g_ps[0][idx] = make_uint2(h2u(__halves2half2(a0, a1)),
                                            h2u(__halves2half2(a2, a3)));
        *(uint2*)&g_ps[1][idx] = make_uint2(h2u(__halves2half2(b0, b1)),
                                            h2u(__halves2half2(b2, b3)));
    }
}

// out[t,b,c,n] = x1 + spike(y2); x1 = ps0 + ps1 (error ~2^-22, output-only)
__global__ void lif_final_t(float* __restrict__ out)
{
    __shared__ float st[32][33];
    int c0 = blockIdx.x * 32, n0 = blockIdx.y * 32, b = blockIdx.z;
    int tx = threadIdx.x & 31, ty = threadIdx.x >> 5;
    float v[4] = {0.f, 0.f, 0.f, 0.f};
    for (int t = 0; t < T_; t++) {
        int tb = t * B_ + b;
        #pragma unroll
        for (int j = 0; j < 4; j++) {
            int n = n0 + ty + 8*j;
            size_t idx = ((size_t)tb * N_ + n) * C_ + c0 + tx;
            float y = g_y2[idx];
            v[j] = v[j] + (y - v[j]) * 0.5f;
            float s = (v[j] >= 1.f) ? 1.f : 0.f;
            if (s != 0.f) v[j] = 0.f;
            float x1 = __half2float(g_ps[0][idx]) + __half2float(g_ps[1][idx]);
            st[tx][ty + 8*j] = x1 + s;
        }
        __syncthreads();
        #pragma unroll
        for (int j = 0; j < 4; j++) {
            int c = c0 + ty + 8*j;
            out[(((size_t)t * B_ + b) * C_ + c) * N_ + n0 + tx] = st[ty + 8*j][tx];
        }
        __syncthreads();
    }
}

// ---------------- attention stage 1: kv = k^T v per (tb,h) --------------------
__global__ __launch_bounds__(256) void attn_kv()
{
    int blk = blockIdx.x;           // tb*8 + h
    int h  = blk & 7;
    int tb = blk >> 3;
    const __half* base = g_qkvh + (size_t)tb * N_ * 768;

    __shared__ float ks[128][33];
    __shared__ float vs[128][36];

    int tid = threadIdx.x;
    int d  = tid >> 3;
    int e4 = (tid & 7) * 4;
    float acc[4] = {0.f, 0.f, 0.f, 0.f};

    for (int n0 = 0; n0 < N_; n0 += 128) {
        for (int i = tid; i < 128 * 32; i += 256) {
            int nl = i >> 5, dd = i & 31;
            const __half* row = base + (size_t)(n0 + nl) * 768 + h * 32;
            ks[nl][dd] = __half2float(row[256 + dd]);
            vs[nl][dd] = __half2float(row[512 + dd]);
        }
        __syncthreads();
        for (int n = 0; n < 128; n++) {
            float kd = ks[n][d];
            float4 vv = *(const float4*)&vs[n][e4];
            acc[0] += kd * vv.x; acc[1] += kd * vv.y;
            acc[2] += kd * vv.z; acc[3] += kd * vv.w;
        }
        __syncthreads();
    }
    float* o = g_kv + (size_t)blk * 1024 + d * 32 + e4;
    o[0] = acc[0]; o[1] = acc[1]; o[2] = acc[2]; o[3] = acc[3];
}

// ---------------- attention stage 2: a = q·kv + fused vth=0.5 LIF -------------
// grid (N/32, B); thread = (n_local, h); 32 e-values; membrane in registers
// across the t-loop. a = 0.125 * integer -> bitwise-identical LIF input.
__global__ __launch_bounds__(256) void attn_apply()
{
    __shared__ float kvs[8 * 32 * 32];   // 32KB [h][d][e]
    int nc = blockIdx.x, b = blockIdx.y;
    int nl = threadIdx.x & 31, h = threadIdx.x >> 5;
    int n  = nc * 32 + nl;
    int tid = threadIdx.x;

    float v[32];
    #pragma unroll
    for (int e = 0; e < 32; e++) v[e] = 0.f;

    for (int t = 0; t < T_; t++) {
        int tb = t * B_ + b;
        for (int i = tid; i < 8 * 1024; i += 256)
            kvs[i] = g_kv[(size_t)(tb * 8) * 1024 + i];
        __syncthreads();

        uint4 qr[4];
        const uint4* qp = (const uint4*)(g_qkvh + ((size_t)tb * N_ + n) * 768 + h * 32);
        qr[0] = qp[0]; qr[1] = qp[1]; qr[2] = qp[2]; qr[3] = qp[3];
        const unsigned short* qv = (const unsigned short*)qr;

        float a[32];
        #pragma unroll
        for (int e = 0; e < 32; e++) a[e] = 0.f;
        #pragma unroll 4
        for (int d = 0; d < 32; d++) {
            if (qv[d] != 0) {
                const float4* kr = (const float4*)&kvs[h * 1024 + d * 32];
                #pragma unroll
                for (int e4 = 0; e4 < 8; e4++) {
                    float4 kk = kr[e4];
                    a[e4*4+0] += kk.x; a[e4*4+1] += kk.y;
                    a[e4*4+2] += kk.z; a[e4*4+3] += kk.w;
                }
            }
        }

        // LIF (vth = 0.5) + pack 32 spikes -> 16 half2 words -> 4x 16B stores
        uint32_t pk[16];
        #pragma unroll
        for (int e2 = 0; e2 < 16; e2++) {
            int e0 = e2 * 2, e1 = e2 * 2 + 1;
            float aa0 = a[e0] * 0.125f;
            float aa1 = a[e1] * 0.125f;
            v[e0] = v[e0] + (aa0 - v[e0]) * 0.5f;
            v[e1] = v[e1] + (aa1 - v[e1]) * 0.5f;
            float s0 = (v[e0] >= 0.5f) ? 1.f : 0.f;
            float s1 = (v[e1] >= 0.5f) ? 1.f : 0.f;
            if (s0 != 0.f) v[e0] = 0.f;
            if (s1 != 0.f) v[e1] = 0.f;
            pk[e2] = h2u(__floats2half2_rn(s0, s1));
        }
        uint4* dst = (uint4*)(g_ab + ((size_t)tb * N_ + n) * 256 + h * 32);
        dst[0] = make_uint4(pk[0],  pk[1],  pk[2],  pk[3]);
        dst[1] = make_uint4(pk[4],  pk[5],  pk[6],  pk[7]);
        dst[2] = make_uint4(pk[8],  pk[9],  pk[10], pk[11]);
        dst[3] = make_uint4(pk[12], pk[13], pk[14], pk[15]);
        __syncthreads();
    }
}

// ---------------- launch -----------------------------------------------------
extern "C" void kernel_launch(void* const* d_in, const int* in_sizes, int n_in,
                              void* d_out, int out_size)
{
    const float* x       = (const float*)d_in[0];
    const float* wq      = (const float*)d_in[2];
    const float* bn_q    = (const float*)d_in[3];
    const float* wk      = (const float*)d_in[4];
    const float* bn_k    = (const float*)d_in[5];
    const float* wv      = (const float*)d_in[6];
    const float* bn_v    = (const float*)d_in[7];
    const float* w_proj  = (const float*)d_in[8];
    const float* b_proj  = (const float*)d_in[9];
    const float* bn_proj = (const float*)d_in[10];
    const float* w_fc1   = (const float*)d_in[11];
    const float* b_fc1   = (const float*)d_in[12];
    const float* bn_fc1  = (const float*)d_in[13];
    const float* w_fc2   = (const float*)d_in[14];
    const float* b_fc2   = (const float*)d_in[15];
    const float* bn_fc2  = (const float*)d_in[16];
    float* out = (float*)d_out;

    __half *wr, *xsp, *ps, *wpb, *wf2b, *ab, *h1b, *qkvh;
    float *qkv, *p, *h1, *y2, *al, *of, *be;
    cudaGetSymbolAddress((void**)&wr,   g_wr);
    cudaGetSymbolAddress((void**)&wpb,  g_wpb);
    cudaGetSymbolAddress((void**)&wf2b, g_wf2b);
    cudaGetSymbolAddress((void**)&xsp,  g_xsp);
    cudaGetSymbolAddress((void**)&ps,   g_ps);
    cudaGetSymbolAddress((void**)&ab,   g_ab);
    cudaGetSymbolAddress((void**)&h1b,  g_h1b);
    cudaGetSymbolAddress((void**)&qkvh, g_qkvh);
    cudaGetSymbolAddress((void**)&qkv,  g_qkv);
    cudaGetSymbolAddress((void**)&p,    g_p);
    cudaGetSymbolAddress((void**)&h1,   g_h1);
    cudaGetSymbolAddress((void**)&y2,   g_y2);
    cudaGetSymbolAddress((void**)&al,   g_alpha);
    cudaGetSymbolAddress((void**)&of,   g_off);
    cudaGetSymbolAddress((void**)&be,   g_beta);

    const int SMEM = 3 * 20480;   // 61440
    cudaFuncSetAttribute(gemm_mma<256,3>,
                         cudaFuncAttributeMaxDynamicSharedMemorySize, SMEM);
    cudaFuncSetAttribute(gemm_mma<256,2>,
                         cudaFuncAttributeMaxDynamicSharedMemorySize, SMEM);
    cudaFuncSetAttribute(gemm_mma<1024,2>,
                         cudaFuncAttributeMaxDynamicSharedMemorySize, SMEM);

    prep_aff<<<1, 256>>>(bn_q, bn_k, bn_v, b_proj, bn_proj, b_fc1, bn_fc1, b_fc2, bn_fc2);
    prep_w_real<<<(WR_SZ + 255)/256, 256>>>(wq, wk, wv, w_fc1);
    prep_w_bin<<<(65536 + 262144 + 255)/256, 256>>>(w_proj, w_fc2);
    transpose_split<<<dim3(8, 32, TB_), 256>>>(x);

    // qkv: M=768, fp16 3-term (real input) -> fp32 preact -> fp16 spikes
    gemm_mma<256,3><<<dim3(8, 6, TB_), 256, SMEM>>>(
        xsp, TCN, wr, WR_SZ, qkv, 768, al + AOFF_QKV, of + AOFF_QKV, be + AOFF_QKV);
    lif_to_half4<<<(int)(S_QKV/4/256), 256>>>(qkv, qkvh, S_QKV, 1.0f);

    // attention: kv precompute, then q-apply with fused vth=0.5 LIF -> g_ab
    attn_kv<<<TB_ * HEADS_, 256>>>();
    attn_apply<<<dim3(N_/32, B_), 256>>>();

    // proj: M=256, fp16 2-term (binary input)
    gemm_mma<256,2><<<dim3(8, 2, TB_), 256, SMEM>>>(
        ab, 0, wpb, 65536, p, 256, al + AOFF_P, of + AOFF_P, be + AOFF_P);
    lif_add_split4<<<(int)(S_C/4/256), 256>>>(p, S_C);

    // fc1: M=1024, fp16 3-term (real input)
    gemm_mma<256,3><<<dim3(8, 8, TB_), 256, SMEM>>>(
        ps, TCN, wr + 768*256, WR_SZ, h1, 1024, al + AOFF_F1, of + AOFF_F1, be + AOFF_F1);
    lif_to_half4<<<(int)(S_H/4/256), 256>>>(h1, h1b, S_H, 1.0f);

    // fc2: M=256, K=1024, fp16 2-term (binary input)
    gemm_mma<1024,2><<<dim3(8, 2, TB_), 256, SMEM>>>(
        h1b, 0, wf2b, 262144, y2, 256, al + AOFF_F2, of + AOFF_F2, be + AOFF_F2);
    lif_final_t<<<dim3(C_/32, N_/32, B_), 256>>>(out);
}

// round 12
// speedup vs baseline: 1.4272x; 1.0148x over previous
#include <cuda_runtime.h>
#include <cuda_fp16.h>
#include <math.h>
#include <stdint.h>

// ---------------- shapes -----------------------------------------------------
#define T_ 4
#define B_ 16
#define C_ 256
#define N_ 1024
#define HD_ 1024
#define HEADS_ 8
#define TB_ (T_*B_)

#define S_C   ((size_t)B_*N_*C_)        // 4,194,304
#define S_QKV ((size_t)B_*N_*768)       // 12,582,912
#define S_H   ((size_t)B_*N_*HD_)       // 16,777,216
#define TCN   ((size_t)T_*S_C)
#define TQKV  ((size_t)T_*S_QKV)
#define THN   ((size_t)T_*S_H)

#define WR_ROWS 1792
#define WR_SZ   (WR_ROWS*256)           // 458752
#define AOFF_QKV  0
#define AOFF_P    768
#define AOFF_F1   1024
#define AOFF_F2   2048
#define ATOT      2304

// ---------------- device scratch ---------------------------------------------
__device__ __half g_wr  [2][WR_SZ];     // fp16 2-split (qkv + fc1 weights)
__device__ __half g_wpb [2][65536];     // fp16 2-split proj weights
__device__ __half g_wf2b[2][262144];    // fp16 2-split fc2 weights
__device__ float g_alpha[ATOT], g_off[ATOT], g_beta[ATOT];

__device__ __half g_xsp [2][TCN];       // x fp16 2-split (x = xsp0+xsp1 ± 2^-22)
__device__ float  g_qkv [TQKV];         // qkv preact fp32
__device__ __half g_qkvh[TQKV];         // qkv spikes fp16
__device__ float  g_kv  [TB_*HEADS_*32*32];  // kv matrices (2MB)
__device__ __half g_ab  [TCN];          // attn spikes fp16
__device__ float  g_p   [TCN];          // proj preact
__device__ __half g_ps  [2][TCN];       // x1 fp16 2-split (x1 = ps0+ps1)
__device__ float  g_h1  [THN];          // fc1 preact
__device__ __half g_h1b [THN];          // fc1 spikes fp16
__device__ float  g_y2  [TCN];          // fc2 preact

// ---------------- helpers ----------------------------------------------------
__device__ __forceinline__ uint32_t smem_u32(const void* p) {
    uint32_t a;
    asm("{ .reg .u64 t; cvta.to.shared.u64 t, %1; cvt.u32.u64 %0, t; }" : "=r"(a) : "l"(p));
    return a;
}
#define CP_ASYNC16(dst, src) \
    asm volatile("cp.async.cg.shared.global [%0], [%1], 16;\n" :: "r"(dst), "l"(src))
#define CP_COMMIT() asm volatile("cp.async.commit_group;\n" ::: "memory")
#define CP_WAIT(n)  asm volatile("cp.async.wait_group %0;\n" :: "n"(n) : "memory")

__device__ __forceinline__ void split2h(float x, __half& a, __half& b) {
    a = __float2half_rn(x); float r = x - __half2float(a);
    b = __float2half_rn(r);
}

__device__ __forceinline__ void mma_f16(float* c, const uint32_t* a, const uint32_t* b) {
    asm volatile("mma.sync.aligned.m16n8k16.row.col.f32.f16.f16.f32 "
        "{%0,%1,%2,%3}, {%4,%5,%6,%7}, {%8,%9}, {%0,%1,%2,%3};"
        : "+f"(c[0]), "+f"(c[1]), "+f"(c[2]), "+f"(c[3])
        : "r"(a[0]), "r"(a[1]), "r"(a[2]), "r"(a[3]), "r"(b[0]), "r"(b[1]));
}

__device__ __forceinline__ uint32_t h2u(__half2 h) {
    return *reinterpret_cast<uint32_t*>(&h);
}

// ---------------- prep kernels -----------------------------------------------
__global__ void prep_aff(const float* __restrict__ bn_q, const float* __restrict__ bn_k,
                         const float* __restrict__ bn_v, const float* __restrict__ b_proj,
                         const float* __restrict__ bn_proj, const float* __restrict__ b_fc1,
                         const float* __restrict__ bn_fc1, const float* __restrict__ b_fc2,
                         const float* __restrict__ bn_fc2)
{
    for (int i = threadIdx.x; i < ATOT; i += blockDim.x) {
        const float* bn; const float* bias = 0; int Cn, ch;
        if (i < 256)       { bn = bn_q;    Cn = 256;  ch = i; }
        else if (i < 512)  { bn = bn_k;    Cn = 256;  ch = i - 256; }
        else if (i < 768)  { bn = bn_v;    Cn = 256;  ch = i - 512; }
        else if (i < 1024) { bn = bn_proj; Cn = 256;  ch = i - 768;  bias = b_proj; }
        else if (i < 2048) { bn = bn_fc1;  Cn = 1024; ch = i - 1024; bias = b_fc1; }
        else               { bn = bn_fc2;  Cn = 256;  ch = i - 2048; bias = b_fc2; }
        float g = bn[0*Cn+ch], be = bn[1*Cn+ch], m = bn[2*Cn+ch], va = bn[3*Cn+ch];
        float rs = (float)(1.0 / sqrt((double)va + 1e-5));
        g_alpha[i] = g * rs;
        g_off[i]   = (bias ? bias[ch] : 0.0f) - m;
        g_beta[i]  = be;
    }
}

__global__ void prep_w_real(const float* __restrict__ wq, const float* __restrict__ wk,
                            const float* __restrict__ wv, const float* __restrict__ wf1)
{
    int i = blockIdx.x * 256 + threadIdx.x;
    if (i >= WR_SZ) return;
    int row = i >> 8, k = i & 255;
    float w;
    if (row < 256)       w = wq[row*256 + k];
    else if (row < 512)  w = wk[(row-256)*256 + k];
    else if (row < 768)  w = wv[(row-512)*256 + k];
    else                 w = wf1[(row-768)*256 + k];
    split2h(w, g_wr[0][i], g_wr[1][i]);
}

__global__ void prep_w_bin(const float* __restrict__ wp, const float* __restrict__ wf2)
{
    int i = blockIdx.x * 256 + threadIdx.x;
    if (i >= 65536 + 262144) return;
    if (i < 65536) split2h(wp[i], g_wpb[0][i], g_wpb[1][i]);
    else { int j = i - 65536; split2h(wf2[j], g_wf2b[0][j], g_wf2b[1][j]); }
}

// x [tb][c][n] -> fp16 2-split planes [tb][n][c] (no fp32 copy kept)
__global__ void transpose_split(const float* __restrict__ x)
{
    __shared__ float tile[32][33];
    int c0 = blockIdx.x * 32, n0 = blockIdx.y * 32, tb = blockIdx.z;
    int tx = threadIdx.x & 31, ty = threadIdx.x >> 5;
    const float* xb = x + (size_t)tb * C_ * N_;
    #pragma unroll
    for (int j = 0; j < 4; j++)
        tile[ty + 8*j][tx] = xb[(size_t)(c0 + ty + 8*j) * N_ + n0 + tx];
    __syncthreads();
    #pragma unroll
    for (int j = 0; j < 4; j++) {
        int n = n0 + ty + 8*j, c = c0 + tx;
        float v = tile[tx][ty + 8*j];
        size_t idx = ((size_t)tb * N_ + n) * C_ + c;
        split2h(v, g_xsp[0][idx], g_xsp[1][idx]);
    }
}

// ---------------- mma.sync fp16 split-GEMM (4-stage pipeline) -----------------
template<int KTOT, int NT>
__global__ __launch_bounds__(256)
void gemm_mma(const __half* __restrict__ Act, size_t actStride,
              const __half* __restrict__ Wt, size_t wStride,
              float* __restrict__ Y, int Mtot,
              const float* __restrict__ alpha, const float* __restrict__ offv,
              const float* __restrict__ beta)
{
    constexpr int KC   = KTOT / 32;
    constexpr int NSEG = NT * KC;
    constexpr int PITCH  = 80;
    constexpr int TILEB  = 128 * PITCH;     // 10240
    constexpr int STAGEB = 2 * TILEB;       // 20480
    constexpr int NSTAGE = 4;

    extern __shared__ char smem[];
    const uint32_t sb = smem_u32(smem);
    const int tid  = threadIdx.x;
    const int lane = tid & 31, warp = tid >> 5;
    const int wn = warp & 1, wm = warp >> 1;
    const int n0 = blockIdx.x * 128, m0 = blockIdx.y * 128;
    const int tbz = blockIdx.z;

    const int WA3[3] = {1,0,0};
    const int XB3[3] = {0,1,0};
    const int WA2[2] = {1,0};
    const int XB2[2] = {0,0};

    const int r_ = tid >> 2, c_ = tid & 3;

    auto load = [&](int seg, int st) {
        if (seg < NSEG) {
            int term = seg / KC, kc = seg - term * KC;
            int wa = (NT == 3) ? WA3[term] : WA2[term];
            int xb = (NT == 3) ? XB3[term] : XB2[term];
            const __half* ap = Act + (size_t)xb * actStride
                          + ((size_t)tbz * N_ + n0) * KTOT + kc * 32;
            const __half* wp = Wt + (size_t)wa * wStride + (size_t)m0 * KTOT + kc * 32;
            uint32_t ab = sb + st * STAGEB, bbs = ab + TILEB;
            #pragma unroll
            for (int j = 0; j < 2; j++) {
                int r = r_ + j * 64;
                CP_ASYNC16(ab  + r * PITCH + c_ * 16, ap + (size_t)r * KTOT + c_ * 8);
                CP_ASYNC16(bbs + r * PITCH + c_ * 16, wp + (size_t)r * KTOT + c_ * 8);
            }
        }
        CP_COMMIT();
    };

    float acc[4][4][4];
    #pragma unroll
    for (int i = 0; i < 4; i++)
        #pragma unroll
        for (int j = 0; j < 4; j++)
            #pragma unroll
            for (int v = 0; v < 4; v++) acc[i][j][v] = 0.0f;

    load(0, 0);
    load(1, 1);
    load(2, 2);

    for (int seg = 0; seg < NSEG; ++seg) {
        CP_WAIT(2);
        __syncthreads();
        load(seg + 3, (seg + 3) % NSTAGE);

        uint32_t ab = sb + (seg % NSTAGE) * STAGEB, bbs = ab + TILEB;
        #pragma unroll
        for (int ki = 0; ki < 2; ki++) {
            uint32_t a[4][4];
            #pragma unroll
            for (int ni = 0; ni < 4; ni++) {
                int row = wn * 64 + ni * 16 + (lane & 15);
                int cc  = ki * 2 + (lane >> 4);
                uint32_t ad = ab + row * PITCH + cc * 16;
                asm volatile("ldmatrix.sync.aligned.m8n8.x4.shared.b16 {%0,%1,%2,%3}, [%4];"
                    : "=r"(a[ni][0]), "=r"(a[ni][1]), "=r"(a[ni][2]), "=r"(a[ni][3])
                    : "r"(ad));
            }
            uint32_t b[4][2];
            #pragma unroll
            for (int mi2 = 0; mi2 < 2; mi2++) {
                int row = wm * 32 + mi2 * 16 + (lane & 7) + ((lane >> 4) << 3);
                int cc  = ki * 2 + ((lane >> 3) & 1);
                uint32_t bd = bbs + row * PITCH + cc * 16;
                uint32_t r0, r1, r2, r3;
                asm volatile("ldmatrix.sync.aligned.m8n8.x4.shared.b16 {%0,%1,%2,%3}, [%4];"
                    : "=r"(r0), "=r"(r1), "=r"(r2), "=r"(r3) : "r"(bd));
                b[mi2*2+0][0] = r0; b[mi2*2+0][1] = r1;
                b[mi2*2+1][0] = r2; b[mi2*2+1][1] = r3;
            }
            #pragma unroll
            for (int ni = 0; ni < 4; ni++)
                #pragma unroll
                for (int mi = 0; mi < 4; mi++)
                    mma_f16(acc[ni][mi], a[ni], b[mi]);
        }
    }

    const int group = lane >> 2, tig = lane & 3;
    #pragma unroll
    for (int mi = 0; mi < 4; mi++) {
        int m = m0 + wm * 32 + mi * 8 + tig * 2;
        float2 al = *(const float2*)&alpha[m];
        float2 of = *(const float2*)&offv[m];
        float2 be = *(const float2*)&beta[m];
        #pragma unroll
        for (int ni = 0; ni < 4; ni++)
            #pragma unroll
            for (int v = 0; v < 2; v++) {
                int n = n0 + wn * 64 + ni * 16 + group + v * 8;
                float2 val;
                val.x = al.x * (acc[ni][mi][v*2+0] + of.x) + be.x;
                val.y = al.y * (acc[ni][mi][v*2+1] + of.y) + be.y;
                *(float2*)&Y[((size_t)tbz * N_ + n) * Mtot + m] = val;
            }
    }
}

// ---------------- LIF kernels (vectorized x4) ---------------------------------
__global__ void lif_to_half4(const float* __restrict__ y, __half* __restrict__ o,
                             size_t S, float vth)
{
    size_t base = ((size_t)blockIdx.x * blockDim.x + threadIdx.x) * 4;
    if (base >= S) return;
    float v0 = 0.f, v1 = 0.f, v2 = 0.f, v3 = 0.f;
    #pragma unroll
    for (int t = 0; t < T_; t++) {
        size_t idx = (size_t)t * S + base;
        float4 xx = *(const float4*)&y[idx];
        v0 = v0 + (xx.x - v0) * 0.5f;
        v1 = v1 + (xx.y - v1) * 0.5f;
        v2 = v2 + (xx.z - v2) * 0.5f;
        v3 = v3 + (xx.w - v3) * 0.5f;
        float s0 = (v0 >= vth) ? 1.f : 0.f;
        float s1 = (v1 >= vth) ? 1.f : 0.f;
        float s2 = (v2 >= vth) ? 1.f : 0.f;
        float s3 = (v3 >= vth) ? 1.f : 0.f;
        if (s0 != 0.f) v0 = 0.f;
        if (s1 != 0.f) v1 = 0.f;
        if (s2 != 0.f) v2 = 0.f;
        if (s3 != 0.f) v3 = 0.f;
        uint2 pk = make_uint2(h2u(__floats2half2_rn(s0, s1)),
                              h2u(__floats2half2_rn(s2, s3)));
        *(uint2*)&o[idx] = pk;
    }
}

// x1 = (xsp0+xsp1) + spike(p); write fp16 2-split of x1
__global__ void lif_add_split4(const float* __restrict__ p, size_t S)
{
    size_t base = ((size_t)blockIdx.x * blockDim.x + threadIdx.x) * 4;
    if (base >= S) return;
    float v0 = 0.f, v1 = 0.f, v2 = 0.f, v3 = 0.f;
    #pragma unroll
    for (int t = 0; t < T_; t++) {
        size_t idx = (size_t)t * S + base;
        float4 pp = *(const float4*)&p[idx];
        uint2 xh0 = *(const uint2*)&g_xsp[0][idx];
        uint2 xh1 = *(const uint2*)&g_xsp[1][idx];
        __half2 xa0 = *reinterpret_cast<__half2*>(&xh0.x);
        __half2 xa1 = *reinterpret_cast<__half2*>(&xh0.y);
        __half2 xb0 = *reinterpret_cast<__half2*>(&xh1.x);
        __half2 xb1 = *reinterpret_cast<__half2*>(&xh1.y);
        float x0 = __half2float(__low2half(xa0))  + __half2float(__low2half(xb0));
        float x1v = __half2float(__high2half(xa0)) + __half2float(__high2half(xb0));
        float x2 = __half2float(__low2half(xa1))  + __half2float(__low2half(xb1));
        float x3 = __half2float(__high2half(xa1)) + __half2float(__high2half(xb1));
        v0 = v0 + (pp.x - v0) * 0.5f;
        v1 = v1 + (pp.y - v1) * 0.5f;
        v2 = v2 + (pp.z - v2) * 0.5f;
        v3 = v3 + (pp.w - v3) * 0.5f;
        float s0 = (v0 >= 1.f) ? 1.f : 0.f;
        float s1 = (v1 >= 1.f) ? 1.f : 0.f;
        float s2 = (v2 >= 1.f) ? 1.f : 0.f;
        float s3 = (v3 >= 1.f) ? 1.f : 0.f;
        if (s0 != 0.f) v0 = 0.f;
        if (s1 != 0.f) v1 = 0.f;
        if (s2 != 0.f) v2 = 0.f;
        if (s3 != 0.f) v3 = 0.f;
        float4 X = make_float4(x0 + s0, x1v + s1, x2 + s2, x3 + s3);
        __half a0, b0, a1, b1, a2, b2, a3, b3;
        split2h(X.x, a0, b0); split2h(X.y, a1, b1);
        split2h(X.z, a2, b2); split2h(X.w, a3, b3);
        *(uint2*)&g_ps[0][idx] = make_uint2(h2u(__halves2half2(a0, a1)),
                                            h2u(__halves2half2(a2, a3)));
        *(uint2*)&g_ps[1][idx] = make_uint2(h2u(__halves2half2(b0, b1)),
                                            h2u(__halves2half2(b2, b3)));
    }
}

// out[t,b,c,n] = x1 + spike(y2); x1 = ps0 + ps1
__global__ void lif_final_t(float* __restrict__ out)
{
    __shared__ float st[32][33];
    int c0 = blockIdx.x * 32, n0 = blockIdx.y * 32, b = blockIdx.z;
    int tx = threadIdx.x & 31, ty = threadIdx.x >> 5;
    float v[4] = {0.f, 0.f, 0.f, 0.f};
    for (int t = 0; t < T_; t++) {
        int tb = t * B_ + b;
        #pragma unroll
        for (int j = 0; j < 4; j++) {
            int n = n0 + ty + 8*j;
            size_t idx = ((size_t)tb * N_ + n) * C_ + c0 + tx;
            float y = g_y2[idx];
            v[j] = v[j] + (y - v[j]) * 0.5f;
            float s = (v[j] >= 1.f) ? 1.f : 0.f;
            if (s != 0.f) v[j] = 0.f;
            float x1 = __half2float(g_ps[0][idx]) + __half2float(g_ps[1][idx]);
            st[tx][ty + 8*j] = x1 + s;
        }
        __syncthreads();
        #pragma unroll
        for (int j = 0; j < 4; j++) {
            int c = c0 + ty + 8*j;
            out[(((size_t)t * B_ + b) * C_ + c) * N_ + n0 + tx] = st[ty + 8*j][tx];
        }
        __syncthreads();
    }
}

// ---------------- attention stage 1: kv = k^T v per (tb,h) --------------------
__global__ __launch_bounds__(256) void attn_kv()
{
    int blk = blockIdx.x;
    int h  = blk & 7;
    int tb = blk >> 3;
    const __half* base = g_qkvh + (size_t)tb * N_ * 768;

    __shared__ float ks[128][33];
    __shared__ float vs[128][36];

    int tid = threadIdx.x;
    int d  = tid >> 3;
    int e4 = (tid & 7) * 4;
    float acc[4] = {0.f, 0.f, 0.f, 0.f};

    for (int n0 = 0; n0 < N_; n0 += 128) {
        for (int i = tid; i < 128 * 32; i += 256) {
            int nl = i >> 5, dd = i & 31;
            const __half* row = base + (size_t)(n0 + nl) * 768 + h * 32;
            ks[nl][dd] = __half2float(row[256 + dd]);
            vs[nl][dd] = __half2float(row[512 + dd]);
        }
        __syncthreads();
        for (int n = 0; n < 128; n++) {
            float kd = ks[n][d];
            float4 vv = *(const float4*)&vs[n][e4];
            acc[0] += kd * vv.x; acc[1] += kd * vv.y;
            acc[2] += kd * vv.z; acc[3] += kd * vv.w;
        }
        __syncthreads();
    }
    float* o = g_kv + (size_t)blk * 1024 + d * 32 + e4;
    o[0] = acc[0]; o[1] = acc[1]; o[2] = acc[2]; o[3] = acc[3];
}

// ---------------- attention stage 2: a = q·kv + fused vth=0.5 LIF -------------
__global__ __launch_bounds__(256) void attn_apply()
{
    __shared__ float kvs[8 * 32 * 32];   // 32KB [h][d][e]
    int nc = blockIdx.x, b = blockIdx.y;
    int nl = threadIdx.x & 31, h = threadIdx.x >> 5;
    int n  = nc * 32 + nl;
    int tid = threadIdx.x;

    float v[32];
    #pragma unroll
    for (int e = 0; e < 32; e++) v[e] = 0.f;

    for (int t = 0; t < T_; t++) {
        int tb = t * B_ + b;
        for (int i = tid; i < 8 * 1024; i += 256)
            kvs[i] = g_kv[(size_t)(tb * 8) * 1024 + i];
        __syncthreads();

        uint4 qr[4];
        const uint4* qp = (const uint4*)(g_qkvh + ((size_t)tb * N_ + n) * 768 + h * 32);
        qr[0] = qp[0]; qr[1] = qp[1]; qr[2] = qp[2]; qr[3] = qp[3];
        const unsigned short* qv = (const unsigned short*)qr;

        float a[32];
        #pragma unroll
        for (int e = 0; e < 32; e++) a[e] = 0.f;
        #pragma unroll 4
        for (int d = 0; d < 32; d++) {
            if (qv[d] != 0) {
                const float4* kr = (const float4*)&kvs[h * 1024 + d * 32];
                #pragma unroll
                for (int e4 = 0; e4 < 8; e4++) {
                    float4 kk = kr[e4];
                    a[e4*4+0] += kk.x; a[e4*4+1] += kk.y;
                    a[e4*4+2] += kk.z; a[e4*4+3] += kk.w;
                }
            }
        }

        uint32_t pk[16];
        #pragma unroll
        for (int e2 = 0; e2 < 16; e2++) {
            int e0 = e2 * 2, e1 = e2 * 2 + 1;
            float aa0 = a[e0] * 0.125f;
            float aa1 = a[e1] * 0.125f;
            v[e0] = v[e0] + (aa0 - v[e0]) * 0.5f;
            v[e1] = v[e1] + (aa1 - v[e1]) * 0.5f;
            float s0 = (v[e0] >= 0.5f) ? 1.f : 0.f;
            float s1 = (v[e1] >= 0.5f) ? 1.f : 0.f;
            if (s0 != 0.f) v[e0] = 0.f;
            if (s1 != 0.f) v[e1] = 0.f;
            pk[e2] = h2u(__floats2half2_rn(s0, s1));
        }
        uint4* dst = (uint4*)(g_ab + ((size_t)tb * N_ + n) * 256 + h * 32);
        dst[0] = make_uint4(pk[0],  pk[1],  pk[2],  pk[3]);
        dst[1] = make_uint4(pk[4],  pk[5],  pk[6],  pk[7]);
        dst[2] = make_uint4(pk[8],  pk[9],  pk[10], pk[11]);
        dst[3] = make_uint4(pk[12], pk[13], pk[14], pk[15]);
        __syncthreads();
    }
}

// ---------------- launch -----------------------------------------------------
extern "C" void kernel_launch(void* const* d_in, const int* in_sizes, int n_in,
                              void* d_out, int out_size)
{
    const float* x       = (const float*)d_in[0];
    const float* wq      = (const float*)d_in[2];
    const float* bn_q    = (const float*)d_in[3];
    const float* wk      = (const float*)d_in[4];
    const float* bn_k    = (const float*)d_in[5];
    const float* wv      = (const float*)d_in[6];
    const float* bn_v    = (const float*)d_in[7];
    const float* w_proj  = (const float*)d_in[8];
    const float* b_proj  = (const float*)d_in[9];
    const float* bn_proj = (const float*)d_in[10];
    const float* w_fc1   = (const float*)d_in[11];
    const float* b_fc1   = (const float*)d_in[12];
    const float* bn_fc1  = (const float*)d_in[13];
    const float* w_fc2   = (const float*)d_in[14];
    const float* b_fc2   = (const float*)d_in[15];
    const float* bn_fc2  = (const float*)d_in[16];
    float* out = (float*)d_out;

    __half *wr, *xsp, *ps, *wpb, *wf2b, *ab, *h1b, *qkvh;
    float *qkv, *p, *h1, *y2, *al, *of, *be;
    cudaGetSymbolAddress((void**)&wr,   g_wr);
    cudaGetSymbolAddress((void**)&wpb,  g_wpb);
    cudaGetSymbolAddress((void**)&wf2b, g_wf2b);
    cudaGetSymbolAddress((void**)&xsp,  g_xsp);
    cudaGetSymbolAddress((void**)&ps,   g_ps);
    cudaGetSymbolAddress((void**)&ab,   g_ab);
    cudaGetSymbolAddress((void**)&h1b,  g_h1b);
    cudaGetSymbolAddress((void**)&qkvh, g_qkvh);
    cudaGetSymbolAddress((void**)&qkv,  g_qkv);
    cudaGetSymbolAddress((void**)&p,    g_p);
    cudaGetSymbolAddress((void**)&h1,   g_h1);
    cudaGetSymbolAddress((void**)&y2,   g_y2);
    cudaGetSymbolAddress((void**)&al,   g_alpha);
    cudaGetSymbolAddress((void**)&of,   g_off);
    cudaGetSymbolAddress((void**)&be,   g_beta);

    const int SMEM = 4 * 20480;   // 81920 (4-stage)
    cudaFuncSetAttribute(gemm_mma<256,3>,
                         cudaFuncAttributeMaxDynamicSharedMemorySize, SMEM);
    cudaFuncSetAttribute(gemm_mma<256,2>,
                         cudaFuncAttributeMaxDynamicSharedMemorySize, SMEM);
    cudaFuncSetAttribute(gemm_mma<1024,2>,
                         cudaFuncAttributeMaxDynamicSharedMemorySize, SMEM);

    prep_aff<<<1, 256>>>(bn_q, bn_k, bn_v, b_proj, bn_proj, b_fc1, bn_fc1, b_fc2, bn_fc2);
    prep_w_real<<<(WR_SZ + 255)/256, 256>>>(wq, wk, wv, w_fc1);
    prep_w_bin<<<(65536 + 262144 + 255)/256, 256>>>(w_proj, w_fc2);
    transpose_split<<<dim3(8, 32, TB_), 256>>>(x);

    // qkv: M=768, fp16 3-term (real input) -> fp32 preact -> fp16 spikes
    gemm_mma<256,3><<<dim3(8, 6, TB_), 256, SMEM>>>(
        xsp, TCN, wr, WR_SZ, qkv, 768, al + AOFF_QKV, of + AOFF_QKV, be + AOFF_QKV);
    lif_to_half4<<<(int)(S_QKV/4/256), 256>>>(qkv, qkvh, S_QKV, 1.0f);

    // attention: kv precompute, then q-apply with fused vth=0.5 LIF -> g_ab
    attn_kv<<<TB_ * HEADS_, 256>>>();
    attn_apply<<<dim3(N_/32, B_), 256>>>();

    // proj: M=256, fp16 2-term (binary input)
    gemm_mma<256,2><<<dim3(8, 2, TB_), 256, SMEM>>>(
        ab, 0, wpb, 65536, p, 256, al + AOFF_P, of + AOFF_P, be + AOFF_P);
    lif_add_split4<<<(int)(S_C/4/256), 256>>>(p, S_C);

    // fc1: M=1024, fp16 3-term (real input)
    gemm_mma<256,3><<<dim3(8, 8, TB_), 256, SMEM>>>(
        ps, TCN, wr + 768*256, WR_SZ, h1, 1024, al + AOFF_F1, of + AOFF_F1, be + AOFF_F1);
    lif_to_half4<<<(int)(S_H/4/256), 256>>>(h1, h1b, S_H, 1.0f);

    // fc2: M=256, K=1024, fp16 2-term (binary input)
    gemm_mma<1024,2><<<dim3(8, 2, TB_), 256, SMEM>>>(
        h1b, 0, wf2b, 262144, y2, 256, al + AOFF_F2, of + AOFF_F2, be + AOFF_F2);
    lif_final_t<<<dim3(C_/32, N_/32, B_), 256>>>(out);
}

// round 13
// speedup vs baseline: 1.4479x; 1.0146x over previous
#include <cuda_runtime.h>
#include <cuda_fp16.h>
#include <math.h>
#include <stdint.h>

// ---------------- shapes -----------------------------------------------------
#define T_ 4
#define B_ 16
#define C_ 256
#define N_ 1024
#define HD_ 1024
#define HEADS_ 8
#define TB_ (T_*B_)

#define S_C   ((size_t)B_*N_*C_)        // 4,194,304
#define S_QKV ((size_t)B_*N_*768)       // 12,582,912
#define S_H   ((size_t)B_*N_*HD_)       // 16,777,216
#define TCN   ((size_t)T_*S_C)
#define TQKV  ((size_t)T_*S_QKV)
#define THN   ((size_t)T_*S_H)

#define WR_ROWS 1792
#define WR_SZ   (WR_ROWS*256)           // 458752
#define AOFF_QKV  0
#define AOFF_P    768
#define AOFF_F1   1024
#define AOFF_F2   2048
#define ATOT      2304

// ---------------- device scratch ---------------------------------------------
__device__ __half g_wr  [2][WR_SZ];     // fp16 2-split (qkv + fc1 weights)
__device__ __half g_wpb [2][65536];     // fp16 2-split proj weights
__device__ __half g_wf2b[2][262144];    // fp16 2-split fc2 weights
__device__ float g_alpha[ATOT], g_off[ATOT], g_beta[ATOT];

__device__ __half   g_xsp [2][TCN];     // x fp16 2-split (x = xsp0+xsp1 ± 2^-22)
__device__ float    g_qkv [TQKV];       // qkv preact fp32
__device__ uint8_t  g_qkvu[TQKV];       // qkv spikes u8 (attention-only consumer)
__device__ float    g_kv  [TB_*HEADS_*32*32];  // kv matrices (2MB)
__device__ __half   g_ab  [TCN];        // attn spikes fp16 (GEMM operand)
__device__ float    g_p   [TCN];        // proj preact
__device__ __half   g_ps  [2][TCN];     // x1 fp16 2-split (x1 = ps0+ps1)
__device__ float    g_h1  [THN];        // fc1 preact
__device__ __half   g_h1b [THN];        // fc1 spikes fp16 (GEMM operand)
__device__ float    g_y2  [TCN];        // fc2 preact

// ---------------- helpers ----------------------------------------------------
__device__ __forceinline__ uint32_t smem_u32(const void* p) {
    uint32_t a;
    asm("{ .reg .u64 t; cvta.to.shared.u64 t, %1; cvt.u32.u64 %0, t; }" : "=r"(a) : "l"(p));
    return a;
}
#define CP_ASYNC16(dst, src) \
    asm volatile("cp.async.cg.shared.global [%0], [%1], 16;\n" :: "r"(dst), "l"(src))
#define CP_COMMIT() asm volatile("cp.async.commit_group;\n" ::: "memory")
#define CP_WAIT(n)  asm volatile("cp.async.wait_group %0;\n" :: "n"(n) : "memory")

__device__ __forceinline__ void split2h(float x, __half& a, __half& b) {
    a = __float2half_rn(x); float r = x - __half2float(a);
    b = __float2half_rn(r);
}

__device__ __forceinline__ void mma_f16(float* c, const uint32_t* a, const uint32_t* b) {
    asm volatile("mma.sync.aligned.m16n8k16.row.col.f32.f16.f16.f32 "
        "{%0,%1,%2,%3}, {%4,%5,%6,%7}, {%8,%9}, {%0,%1,%2,%3};"
        : "+f"(c[0]), "+f"(c[1]), "+f"(c[2]), "+f"(c[3])
        : "r"(a[0]), "r"(a[1]), "r"(a[2]), "r"(a[3]), "r"(b[0]), "r"(b[1]));
}

__device__ __forceinline__ uint32_t h2u(__half2 h) {
    return *reinterpret_cast<uint32_t*>(&h);
}

// ---------------- prep kernels -----------------------------------------------
__global__ void prep_aff(const float* __restrict__ bn_q, const float* __restrict__ bn_k,
                         const float* __restrict__ bn_v, const float* __restrict__ b_proj,
                         const float* __restrict__ bn_proj, const float* __restrict__ b_fc1,
                         const float* __restrict__ bn_fc1, const float* __restrict__ b_fc2,
                         const float* __restrict__ bn_fc2)
{
    for (int i = threadIdx.x; i < ATOT; i += blockDim.x) {
        const float* bn; const float* bias = 0; int Cn, ch;
        if (i < 256)       { bn = bn_q;    Cn = 256;  ch = i; }
        else if (i < 512)  { bn = bn_k;    Cn = 256;  ch = i - 256; }
        else if (i < 768)  { bn = bn_v;    Cn = 256;  ch = i - 512; }
        else if (i < 1024) { bn = bn_proj; Cn = 256;  ch = i - 768;  bias = b_proj; }
        else if (i < 2048) { bn = bn_fc1;  Cn = 1024; ch = i - 1024; bias = b_fc1; }
        else               { bn = bn_fc2;  Cn = 256;  ch = i - 2048; bias = b_fc2; }
        float g = bn[0*Cn+ch], be = bn[1*Cn+ch], m = bn[2*Cn+ch], va = bn[3*Cn+ch];
        float rs = (float)(1.0 / sqrt((double)va + 1e-5));
        g_alpha[i] = g * rs;
        g_off[i]   = (bias ? bias[ch] : 0.0f) - m;
        g_beta[i]  = be;
    }
}

__global__ void prep_w_real(const float* __restrict__ wq, const float* __restrict__ wk,
                            const float* __restrict__ wv, const float* __restrict__ wf1)
{
    int i = blockIdx.x * 256 + threadIdx.x;
    if (i >= WR_SZ) return;
    int row = i >> 8, k = i & 255;
    float w;
    if (row < 256)       w = wq[row*256 + k];
    else if (row < 512)  w = wk[(row-256)*256 + k];
    else if (row < 768)  w = wv[(row-512)*256 + k];
    else                 w = wf1[(row-768)*256 + k];
    split2h(w, g_wr[0][i], g_wr[1][i]);
}

__global__ void prep_w_bin(const float* __restrict__ wp, const float* __restrict__ wf2)
{
    int i = blockIdx.x * 256 + threadIdx.x;
    if (i >= 65536 + 262144) return;
    if (i < 65536) split2h(wp[i], g_wpb[0][i], g_wpb[1][i]);
    else { int j = i - 65536; split2h(wf2[j], g_wf2b[0][j], g_wf2b[1][j]); }
}

// x [tb][c][n] -> fp16 2-split planes [tb][n][c]
__global__ void transpose_split(const float* __restrict__ x)
{
    __shared__ float tile[32][33];
    int c0 = blockIdx.x * 32, n0 = blockIdx.y * 32, tb = blockIdx.z;
    int tx = threadIdx.x & 31, ty = threadIdx.x >> 5;
    const float* xb = x + (size_t)tb * C_ * N_;
    #pragma unroll
    for (int j = 0; j < 4; j++)
        tile[ty + 8*j][tx] = xb[(size_t)(c0 + ty + 8*j) * N_ + n0 + tx];
    __syncthreads();
    #pragma unroll
    for (int j = 0; j < 4; j++) {
        int n = n0 + ty + 8*j, c = c0 + tx;
        float v = tile[tx][ty + 8*j];
        size_t idx = ((size_t)tb * N_ + n) * C_ + c;
        split2h(v, g_xsp[0][idx], g_xsp[1][idx]);
    }
}

// ---------------- mma.sync fp16 split-GEMM (4-stage pipeline) -----------------
template<int KTOT, int NT>
__global__ __launch_bounds__(256)
void gemm_mma(const __half* __restrict__ Act, size_t actStride,
              const __half* __restrict__ Wt, size_t wStride,
              float* __restrict__ Y, int Mtot,
              const float* __restrict__ alpha, const float* __restrict__ offv,
              const float* __restrict__ beta)
{
    constexpr int KC   = KTOT / 32;
    constexpr int NSEG = NT * KC;
    constexpr int PITCH  = 80;
    constexpr int TILEB  = 128 * PITCH;
    constexpr int STAGEB = 2 * TILEB;
    constexpr int NSTAGE = 4;

    extern __shared__ char smem[];
    const uint32_t sb = smem_u32(smem);
    const int tid  = threadIdx.x;
    const int lane = tid & 31, warp = tid >> 5;
    const int wn = warp & 1, wm = warp >> 1;
    const int n0 = blockIdx.x * 128, m0 = blockIdx.y * 128;
    const int tbz = blockIdx.z;

    const int WA3[3] = {1,0,0};
    const int XB3[3] = {0,1,0};
    const int WA2[2] = {1,0};
    const int XB2[2] = {0,0};

    const int r_ = tid >> 2, c_ = tid & 3;

    auto load = [&](int seg, int st) {
        if (seg < NSEG) {
            int term = seg / KC, kc = seg - term * KC;
            int wa = (NT == 3) ? WA3[term] : WA2[term];
            int xb = (NT == 3) ? XB3[term] : XB2[term];
            const __half* ap = Act + (size_t)xb * actStride
                          + ((size_t)tbz * N_ + n0) * KTOT + kc * 32;
            const __half* wp = Wt + (size_t)wa * wStride + (size_t)m0 * KTOT + kc * 32;
            uint32_t ab = sb + st * STAGEB, bbs = ab + TILEB;
            #pragma unroll
            for (int j = 0; j < 2; j++) {
                int r = r_ + j * 64;
                CP_ASYNC16(ab  + r * PITCH + c_ * 16, ap + (size_t)r * KTOT + c_ * 8);
                CP_ASYNC16(bbs + r * PITCH + c_ * 16, wp + (size_t)r * KTOT + c_ * 8);
            }
        }
        CP_COMMIT();
    };

    float acc[4][4][4];
    #pragma unroll
    for (int i = 0; i < 4; i++)
        #pragma unroll
        for (int j = 0; j < 4; j++)
            #pragma unroll
            for (int v = 0; v < 4; v++) acc[i][j][v] = 0.0f;

    load(0, 0);
    load(1, 1);
    load(2, 2);

    for (int seg = 0; seg < NSEG; ++seg) {
        CP_WAIT(2);
        __syncthreads();
        load(seg + 3, (seg + 3) % NSTAGE);

        uint32_t ab = sb + (seg % NSTAGE) * STAGEB, bbs = ab + TILEB;
        #pragma unroll
        for (int ki = 0; ki < 2; ki++) {
            uint32_t a[4][4];
            #pragma unroll
            for (int ni = 0; ni < 4; ni++) {
                int row = wn * 64 + ni * 16 + (lane & 15);
                int cc  = ki * 2 + (lane >> 4);
                uint32_t ad = ab + row * PITCH + cc * 16;
                asm volatile("ldmatrix.sync.aligned.m8n8.x4.shared.b16 {%0,%1,%2,%3}, [%4];"
                    : "=r"(a[ni][0]), "=r"(a[ni][1]), "=r"(a[ni][2]), "=r"(a[ni][3])
                    : "r"(ad));
            }
            uint32_t b[4][2];
            #pragma unroll
            for (int mi2 = 0; mi2 < 2; mi2++) {
                int row = wm * 32 + mi2 * 16 + (lane & 7) + ((lane >> 4) << 3);
                int cc  = ki * 2 + ((lane >> 3) & 1);
                uint32_t bd = bbs + row * PITCH + cc * 16;
                uint32_t r0, r1, r2, r3;
                asm volatile("ldmatrix.sync.aligned.m8n8.x4.shared.b16 {%0,%1,%2,%3}, [%4];"
                    : "=r"(r0), "=r"(r1), "=r"(r2), "=r"(r3) : "r"(bd));
                b[mi2*2+0][0] = r0; b[mi2*2+0][1] = r1;
                b[mi2*2+1][0] = r2; b[mi2*2+1][1] = r3;
            }
            #pragma unroll
            for (int ni = 0; ni < 4; ni++)
                #pragma unroll
                for (int mi = 0; mi < 4; mi++)
                    mma_f16(acc[ni][mi], a[ni], b[mi]);
        }
    }

    const int group = lane >> 2, tig = lane & 3;
    #pragma unroll
    for (int mi = 0; mi < 4; mi++) {
        int m = m0 + wm * 32 + mi * 8 + tig * 2;
        float2 al = *(const float2*)&alpha[m];
        float2 of = *(const float2*)&offv[m];
        float2 be = *(const float2*)&beta[m];
        #pragma unroll
        for (int ni = 0; ni < 4; ni++)
            #pragma unroll
            for (int v = 0; v < 2; v++) {
                int n = n0 + wn * 64 + ni * 16 + group + v * 8;
                float2 val;
                val.x = al.x * (acc[ni][mi][v*2+0] + of.x) + be.x;
                val.y = al.y * (acc[ni][mi][v*2+1] + of.y) + be.y;
                *(float2*)&Y[((size_t)tbz * N_ + n) * Mtot + m] = val;
            }
    }
}

// ---------------- LIF kernels (vectorized x4) ---------------------------------
// spikes -> u8 (attention-path consumer)
__global__ void lif_to_u8_4(const float* __restrict__ y, uint8_t* __restrict__ o,
                            size_t S, float vth)
{
    size_t base = ((size_t)blockIdx.x * blockDim.x + threadIdx.x) * 4;
    if (base >= S) return;
    float v0 = 0.f, v1 = 0.f, v2 = 0.f, v3 = 0.f;
    #pragma unroll
    for (int t = 0; t < T_; t++) {
        size_t idx = (size_t)t * S + base;
        float4 xx = *(const float4*)&y[idx];
        v0 = v0 + (xx.x - v0) * 0.5f;
        v1 = v1 + (xx.y - v1) * 0.5f;
        v2 = v2 + (xx.z - v2) * 0.5f;
        v3 = v3 + (xx.w - v3) * 0.5f;
        uint32_t s0 = (v0 >= vth) ? 1u : 0u;
        uint32_t s1 = (v1 >= vth) ? 1u : 0u;
        uint32_t s2 = (v2 >= vth) ? 1u : 0u;
        uint32_t s3 = (v3 >= vth) ? 1u : 0u;
        if (s0) v0 = 0.f;
        if (s1) v1 = 0.f;
        if (s2) v2 = 0.f;
        if (s3) v3 = 0.f;
        *(uint32_t*)&o[idx] = s0 | (s1 << 8) | (s2 << 16) | (s3 << 24);
    }
}

// spikes -> fp16 (GEMM-operand consumer)
__global__ void lif_to_half4(const float* __restrict__ y, __half* __restrict__ o,
                             size_t S, float vth)
{
    size_t base = ((size_t)blockIdx.x * blockDim.x + threadIdx.x) * 4;
    if (base >= S) return;
    float v0 = 0.f, v1 = 0.f, v2 = 0.f, v3 = 0.f;
    #pragma unroll
    for (int t = 0; t < T_; t++) {
        size_t idx = (size_t)t * S + base;
        float4 xx = *(const float4*)&y[idx];
        v0 = v0 + (xx.x - v0) * 0.5f;
        v1 = v1 + (xx.y - v1) * 0.5f;
        v2 = v2 + (xx.z - v2) * 0.5f;
        v3 = v3 + (xx.w - v3) * 0.5f;
        float s0 = (v0 >= vth) ? 1.f : 0.f;
        float s1 = (v1 >= vth) ? 1.f : 0.f;
        float s2 = (v2 >= vth) ? 1.f : 0.f;
        float s3 = (v3 >= vth) ? 1.f : 0.f;
        if (s0 != 0.f) v0 = 0.f;
        if (s1 != 0.f) v1 = 0.f;
        if (s2 != 0.f) v2 = 0.f;
        if (s3 != 0.f) v3 = 0.f;
        uint2 pk = make_uint2(h2u(__floats2half2_rn(s0, s1)),
                              h2u(__floats2half2_rn(s2, s3)));
        *(uint2*)&o[idx] = pk;
    }
}

// x1 = (xsp0+xsp1) + spike(p); write fp16 2-split of x1
__global__ void lif_add_split4(const float* __restrict__ p, size_t S)
{
    size_t base = ((size_t)blockIdx.x * blockDim.x + threadIdx.x) * 4;
    if (base >= S) return;
    float v0 = 0.f, v1 = 0.f, v2 = 0.f, v3 = 0.f;
    #pragma unroll
    for (int t = 0; t < T_; t++) {
        size_t idx = (size_t)t * S + base;
        float4 pp = *(const float4*)&p[idx];
        uint2 xh0 = *(const uint2*)&g_xsp[0][idx];
        uint2 xh1 = *(const uint2*)&g_xsp[1][idx];
        __half2 xa0 = *reinterpret_cast<__half2*>(&xh0.x);
        __half2 xa1 = *reinterpret_cast<__half2*>(&xh0.y);
        __half2 xb0 = *reinterpret_cast<__half2*>(&xh1.x);
        __half2 xb1 = *reinterpret_cast<__half2*>(&xh1.y);
        float x0 = __half2float(__low2half(xa0))  + __half2float(__low2half(xb0));
        float x1v = __half2float(__high2half(xa0)) + __half2float(__high2half(xb0));
        float x2 = __half2float(__low2half(xa1))  + __half2float(__low2half(xb1));
        float x3 = __half2float(__high2half(xa1)) + __half2float(__high2half(xb1));
        v0 = v0 + (pp.x - v0) * 0.5f;
        v1 = v1 + (pp.y - v1) * 0.5f;
        v2 = v2 + (pp.z - v2) * 0.5f;
        v3 = v3 + (pp.w - v3) * 0.5f;
        float s0 = (v0 >= 1.f) ? 1.f : 0.f;
        float s1 = (v1 >= 1.f) ? 1.f : 0.f;
        float s2 = (v2 >= 1.f) ? 1.f : 0.f;
        float s3 = (v3 >= 1.f) ? 1.f : 0.f;
        if (s0 != 0.f) v0 = 0.f;
        if (s1 != 0.f) v1 = 0.f;
        if (s2 != 0.f) v2 = 0.f;
        if (s3 != 0.f) v3 = 0.f;
        float4 X = make_float4(x0 + s0, x1v + s1, x2 + s2, x3 + s3);
        __half a0, b0, a1, b1, a2, b2, a3, b3;
        split2h(X.x, a0, b0); split2h(X.y, a1, b1);
        split2h(X.z, a2, b2); split2h(X.w, a3, b3);
        *(uint2*)&g_ps[0][idx] = make_uint2(h2u(__halves2half2(a0, a1)),
                                            h2u(__halves2half2(a2, a3)));
        *(uint2*)&g_ps[1][idx] = make_uint2(h2u(__halves2half2(b0, b1)),
                                            h2u(__halves2half2(b2, b3)));
    }
}

// out[t,b,c,n] = x1 + spike(y2); x1 = ps0 + ps1
__global__ void lif_final_t(float* __restrict__ out)
{
    __shared__ float st[32][33];
    int c0 = blockIdx.x * 32, n0 = blockIdx.y * 32, b = blockIdx.z;
    int tx = threadIdx.x & 31, ty = threadIdx.x >> 5;
    float v[4] = {0.f, 0.f, 0.f, 0.f};
    for (int t = 0; t < T_; t++) {
        int tb = t * B_ + b;
        #pragma unroll
        for (int j = 0; j < 4; j++) {
            int n = n0 + ty + 8*j;
            size_t idx = ((size_t)tb * N_ + n) * C_ + c0 + tx;
            float y = g_y2[idx];
            v[j] = v[j] + (y - v[j]) * 0.5f;
            float s = (v[j] >= 1.f) ? 1.f : 0.f;
            if (s != 0.f) v[j] = 0.f;
            float x1 = __half2float(g_ps[0][idx]) + __half2float(g_ps[1][idx]);
            st[tx][ty + 8*j] = x1 + s;
        }
        __syncthreads();
        #pragma unroll
        for (int j = 0; j < 4; j++) {
            int c = c0 + ty + 8*j;
            out[(((size_t)t * B_ + b) * C_ + c) * N_ + n0 + tx] = st[ty + 8*j][tx];
        }
        __syncthreads();
    }
}

// ---------------- attention stage 1: kv = k^T v per (tb,h) (u8 spikes) --------
__global__ __launch_bounds__(256) void attn_kv()
{
    int blk = blockIdx.x;
    int h  = blk & 7;
    int tb = blk >> 3;
    const uint8_t* base = g_qkvu + (size_t)tb * N_ * 768;

    __shared__ float ks[128][33];
    __shared__ float vs[128][36];

    int tid = threadIdx.x;
    int d  = tid >> 3;
    int e4 = (tid & 7) * 4;
    float acc[4] = {0.f, 0.f, 0.f, 0.f};

    for (int n0 = 0; n0 < N_; n0 += 128) {
        for (int i = tid; i < 128 * 32; i += 256) {
            int nl = i >> 5, dd = i & 31;
            const uint8_t* row = base + (size_t)(n0 + nl) * 768 + h * 32;
            ks[nl][dd] = (float)row[256 + dd];
            vs[nl][dd] = (float)row[512 + dd];
        }
        __syncthreads();
        for (int n = 0; n < 128; n++) {
            float kd = ks[n][d];
            float4 vv = *(const float4*)&vs[n][e4];
            acc[0] += kd * vv.x; acc[1] += kd * vv.y;
            acc[2] += kd * vv.z; acc[3] += kd * vv.w;
        }
        __syncthreads();
    }
    float* o = g_kv + (size_t)blk * 1024 + d * 32 + e4;
    o[0] = acc[0]; o[1] = acc[1]; o[2] = acc[2]; o[3] = acc[3];
}

// ---------------- attention stage 2: a = q·kv + fused vth=0.5 LIF -------------
__global__ __launch_bounds__(256) void attn_apply()
{
    __shared__ float kvs[8 * 32 * 32];   // 32KB [h][d][e]
    int nc = blockIdx.x, b = blockIdx.y;
    int nl = threadIdx.x & 31, h = threadIdx.x >> 5;
    int n  = nc * 32 + nl;
    int tid = threadIdx.x;

    float v[32];
    #pragma unroll
    for (int e = 0; e < 32; e++) v[e] = 0.f;

    for (int t = 0; t < T_; t++) {
        int tb = t * B_ + b;
        for (int i = tid; i < 8 * 1024; i += 256)
            kvs[i] = g_kv[(size_t)(tb * 8) * 1024 + i];
        __syncthreads();

        // q spikes for this (n,h): 32 bytes = 2x 16B loads
        uint4 qr[2];
        const uint4* qp = (const uint4*)(g_qkvu + ((size_t)tb * N_ + n) * 768 + h * 32);
        qr[0] = qp[0]; qr[1] = qp[1];
        const uint8_t* qv = (const uint8_t*)qr;

        float a[32];
        #pragma unroll
        for (int e = 0; e < 32; e++) a[e] = 0.f;
        #pragma unroll 4
        for (int d = 0; d < 32; d++) {
            if (qv[d] != 0) {
                const float4* kr = (const float4*)&kvs[h * 1024 + d * 32];
                #pragma unroll
                for (int e4 = 0; e4 < 8; e4++) {
                    float4 kk = kr[e4];
                    a[e4*4+0] += kk.x; a[e4*4+1] += kk.y;
                    a[e4*4+2] += kk.z; a[e4*4+3] += kk.w;
                }
            }
        }

        uint32_t pk[16];
        #pragma unroll
        for (int e2 = 0; e2 < 16; e2++) {
            int e0 = e2 * 2, e1 = e2 * 2 + 1;
            float aa0 = a[e0] * 0.125f;
            float aa1 = a[e1] * 0.125f;
            v[e0] = v[e0] + (aa0 - v[e0]) * 0.5f;
            v[e1] = v[e1] + (aa1 - v[e1]) * 0.5f;
            float s0 = (v[e0] >= 0.5f) ? 1.f : 0.f;
            float s1 = (v[e1] >= 0.5f) ? 1.f : 0.f;
            if (s0 != 0.f) v[e0] = 0.f;
            if (s1 != 0.f) v[e1] = 0.f;
            pk[e2] = h2u(__floats2half2_rn(s0, s1));
        }
        uint4* dst = (uint4*)(g_ab + ((size_t)tb * N_ + n) * 256 + h * 32);
        dst[0] = make_uint4(pk[0],  pk[1],  pk[2],  pk[3]);
        dst[1] = make_uint4(pk[4],  pk[5],  pk[6],  pk[7]);
        dst[2] = make_uint4(pk[8],  pk[9],  pk[10], pk[11]);
        dst[3] = make_uint4(pk[12], pk[13], pk[14], pk[15]);
        __syncthreads();
    }
}

// ---------------- launch -----------------------------------------------------
extern "C" void kernel_launch(void* const* d_in, const int* in_sizes, int n_in,
                              void* d_out, int out_size)
{
    const float* x       = (const float*)d_in[0];
    const float* wq      = (const float*)d_in[2];
    const float* bn_q    = (const float*)d_in[3];
    const float* wk      = (const float*)d_in[4];
    const float* bn_k    = (const float*)d_in[5];
    const float* wv      = (const float*)d_in[6];
    const float* bn_v    = (const float*)d_in[7];
    const float* w_proj  = (const float*)d_in[8];
    const float* b_proj  = (const float*)d_in[9];
    const float* bn_proj = (const float*)d_in[10];
    const float* w_fc1   = (const float*)d_in[11];
    const float* b_fc1   = (const float*)d_in[12];
    const float* bn_fc1  = (const float*)d_in[13];
    const float* w_fc2   = (const float*)d_in[14];
    const float* b_fc2   = (const float*)d_in[15];
    const float* bn_fc2  = (const float*)d_in[16];
    float* out = (float*)d_out;

    __half *wr, *xsp, *ps, *wpb, *wf2b, *ab, *h1b;
    uint8_t *qkvu;
    float *qkv, *p, *h1, *y2, *al, *of, *be;
    cudaGetSymbolAddress((void**)&wr,   g_wr);
    cudaGetSymbolAddress((void**)&wpb,  g_wpb);
    cudaGetSymbolAddress((void**)&wf2b, g_wf2b);
    cudaGetSymbolAddress((void**)&xsp,  g_xsp);
    cudaGetSymbolAddress((void**)&ps,   g_ps);
    cudaGetSymbolAddress((void**)&ab,   g_ab);
    cudaGetSymbolAddress((void**)&h1b,  g_h1b);
    cudaGetSymbolAddress((void**)&qkvu, g_qkvu);
    cudaGetSymbolAddress((void**)&qkv,  g_qkv);
    cudaGetSymbolAddress((void**)&p,    g_p);
    cudaGetSymbolAddress((void**)&h1,   g_h1);
    cudaGetSymbolAddress((void**)&y2,   g_y2);
    cudaGetSymbolAddress((void**)&al,   g_alpha);
    cudaGetSymbolAddress((void**)&of,   g_off);
    cudaGetSymbolAddress((void**)&be,   g_beta);

    const int SMEM = 4 * 20480;   // 81920 (4-stage)
    cudaFuncSetAttribute(gemm_mma<256,3>,
                         cudaFuncAttributeMaxDynamicSharedMemorySize, SMEM);
    cudaFuncSetAttribute(gemm_mma<256,2>,
                         cudaFuncAttributeMaxDynamicSharedMemorySize, SMEM);
    cudaFuncSetAttribute(gemm_mma<1024,2>,
                         cudaFuncAttributeMaxDynamicSharedMemorySize, SMEM);

    prep_aff<<<1, 256>>>(bn_q, bn_k, bn_v, b_proj, bn_proj, b_fc1, bn_fc1, b_fc2, bn_fc2);
    prep_w_real<<<(WR_SZ + 255)/256, 256>>>(wq, wk, wv, w_fc1);
    prep_w_bin<<<(65536 + 262144 + 255)/256, 256>>>(w_proj, w_fc2);
    transpose_split<<<dim3(8, 32, TB_), 256>>>(x);

    // qkv: M=768, fp16 3-term (real input) -> fp32 preact -> u8 spikes
    gemm_mma<256,3><<<dim3(8, 6, TB_), 256, SMEM>>>(
        xsp, TCN, wr, WR_SZ, qkv, 768, al + AOFF_QKV, of + AOFF_QKV, be + AOFF_QKV);
    lif_to_u8_4<<<(int)(S_QKV/4/256), 256>>>(qkv, qkvu, S_QKV, 1.0f);

    // attention: kv precompute, then q-apply with fused vth=0.5 LIF -> g_ab
    attn_kv<<<TB_ * HEADS_, 256>>>();
    attn_apply<<<dim3(N_/32, B_), 256>>>();

    // proj: M=256, fp16 2-term (binary input)
    gemm_mma<256,2><<<dim3(8, 2, TB_), 256, SMEM>>>(
        ab, 0, wpb, 65536, p, 256, al + AOFF_P, of + AOFF_P, be + AOFF_P);
    lif_add_split4<<<(int)(S_C/4/256), 256>>>(p, S_C);

    // fc1: M=1024, fp16 3-term (real input)
    gemm_mma<256,3><<<dim3(8, 8, TB_), 256, SMEM>>>(
        ps, TCN, wr + 768*256, WR_SZ, h1, 1024, al + AOFF_F1, of + AOFF_F1, be + AOFF_F1);
    lif_to_half4<<<(int)(S_H/4/256), 256>>>(h1, h1b, S_H, 1.0f);

    // fc2: M=256, K=1024, fp16 2-term (binary input)
    gemm_mma<1024,2><<<dim3(8, 2, TB_), 256, SMEM>>>(
        h1b, 0, wf2b, 262144, y2, 256, al + AOFF_F2, of + AOFF_F2, be + AOFF_F2);
    lif_final_t<<<dim3(C_/32, N_/32, B_), 256>>>(out);
}

// round 14
// speedup vs baseline: 1.4551x; 1.0049x over previous
#include <cuda_runtime.h>
#include <cuda_fp16.h>
#include <math.h>
#include <stdint.h>

// ---------------- shapes -----------------------------------------------------
#define T_ 4
#define B_ 16
#define C_ 256
#define N_ 1024
#define HD_ 1024
#define HEADS_ 8
#define TB_ (T_*B_)

#define S_C   ((size_t)B_*N_*C_)        // 4,194,304
#define S_QKV ((size_t)B_*N_*768)
#define S_H   ((size_t)B_*N_*HD_)
#define TCN   ((size_t)T_*S_C)
#define TQKV  ((size_t)T_*S_QKV)
#define THN   ((size_t)T_*S_H)

#define WR_ROWS 1792
#define WR_SZ   (WR_ROWS*256)           // 458752
#define AOFF_QKV  0
#define AOFF_P    768
#define AOFF_F1   1024
#define AOFF_F2   2048
#define ATOT      2304

// ---------------- device scratch ---------------------------------------------
__device__ __half g_wr  [2][WR_SZ];     // fp16 2-split (qkv + fc1 weights)
__device__ __half g_wpb [2][65536];     // fp16 2-split proj weights
__device__ __half g_wf2b[2][262144];    // fp16 2-split fc2 weights
__device__ float g_alpha[ATOT], g_off[ATOT], g_beta[ATOT];

__device__ __half   g_xsp [2][TCN];     // x fp16 2-split
__device__ uint8_t  g_qkvu[TQKV];       // qkv spikes u8 (from fused epilogue)
__device__ float    g_kv  [TB_*HEADS_*32*32];
__device__ __half   g_ab  [TCN];        // attn spikes fp16 (GEMM operand)
__device__ float    g_p   [TCN];        // proj preact
__device__ __half   g_ps  [2][TCN];     // x1 fp16 2-split
__device__ __half   g_h1b [THN];        // fc1 spikes fp16 (from fused epilogue)
__device__ float    g_y2  [TCN];        // fc2 preact

// ---------------- helpers ----------------------------------------------------
__device__ __forceinline__ uint32_t smem_u32(const void* p) {
    uint32_t a;
    asm("{ .reg .u64 t; cvta.to.shared.u64 t, %1; cvt.u32.u64 %0, t; }" : "=r"(a) : "l"(p));
    return a;
}
#define CP_ASYNC16(dst, src) \
    asm volatile("cp.async.cg.shared.global [%0], [%1], 16;\n" :: "r"(dst), "l"(src))
#define CP_COMMIT() asm volatile("cp.async.commit_group;\n" ::: "memory")
#define CP_WAIT(n)  asm volatile("cp.async.wait_group %0;\n" :: "n"(n) : "memory")

__device__ __forceinline__ void split2h(float x, __half& a, __half& b) {
    a = __float2half_rn(x); float r = x - __half2float(a);
    b = __float2half_rn(r);
}

__device__ __forceinline__ void mma_f16(float* c, const uint32_t* a, const uint32_t* b) {
    asm volatile("mma.sync.aligned.m16n8k16.row.col.f32.f16.f16.f32 "
        "{%0,%1,%2,%3}, {%4,%5,%6,%7}, {%8,%9}, {%0,%1,%2,%3};"
        : "+f"(c[0]), "+f"(c[1]), "+f"(c[2]), "+f"(c[3])
        : "r"(a[0]), "r"(a[1]), "r"(a[2]), "r"(a[3]), "r"(b[0]), "r"(b[1]));
}

__device__ __forceinline__ uint32_t h2u(__half2 h) {
    return *reinterpret_cast<uint32_t*>(&h);
}

// ---------------- prep kernels -----------------------------------------------
__global__ void prep_aff(const float* __restrict__ bn_q, const float* __restrict__ bn_k,
                         const float* __restrict__ bn_v, const float* __restrict__ b_proj,
                         const float* __restrict__ bn_proj, const float* __restrict__ b_fc1,
                         const float* __restrict__ bn_fc1, const float* __restrict__ b_fc2,
                         const float* __restrict__ bn_fc2)
{
    for (int i = threadIdx.x; i < ATOT; i += blockDim.x) {
        const float* bn; const float* bias = 0; int Cn, ch;
        if (i < 256)       { bn = bn_q;    Cn = 256;  ch = i; }
        else if (i < 512)  { bn = bn_k;    Cn = 256;  ch = i - 256; }
        else if (i < 768)  { bn = bn_v;    Cn = 256;  ch = i - 512; }
        else if (i < 1024) { bn = bn_proj; Cn = 256;  ch = i - 768;  bias = b_proj; }
        else if (i < 2048) { bn = bn_fc1;  Cn = 1024; ch = i - 1024; bias = b_fc1; }
        else               { bn = bn_fc2;  Cn = 256;  ch = i - 2048; bias = b_fc2; }
        float g = bn[0*Cn+ch], be = bn[1*Cn+ch], m = bn[2*Cn+ch], va = bn[3*Cn+ch];
        float rs = (float)(1.0 / sqrt((double)va + 1e-5));
        g_alpha[i] = g * rs;
        g_off[i]   = (bias ? bias[ch] : 0.0f) - m;
        g_beta[i]  = be;
    }
}

__global__ void prep_w_real(const float* __restrict__ wq, const float* __restrict__ wk,
                            const float* __restrict__ wv, const float* __restrict__ wf1)
{
    int i = blockIdx.x * 256 + threadIdx.x;
    if (i >= WR_SZ) return;
    int row = i >> 8, k = i & 255;
    float w;
    if (row < 256)       w = wq[row*256 + k];
    else if (row < 512)  w = wk[(row-256)*256 + k];
    else if (row < 768)  w = wv[(row-512)*256 + k];
    else                 w = wf1[(row-768)*256 + k];
    split2h(w, g_wr[0][i], g_wr[1][i]);
}

__global__ void prep_w_bin(const float* __restrict__ wp, const float* __restrict__ wf2)
{
    int i = blockIdx.x * 256 + threadIdx.x;
    if (i >= 65536 + 262144) return;
    if (i < 65536) split2h(wp[i], g_wpb[0][i], g_wpb[1][i]);
    else { int j = i - 65536; split2h(wf2[j], g_wf2b[0][j], g_wf2b[1][j]); }
}

// x [tb][c][n] -> fp16 2-split planes [tb][n][c]
__global__ void transpose_split(const float* __restrict__ x)
{
    __shared__ float tile[32][33];
    int c0 = blockIdx.x * 32, n0 = blockIdx.y * 32, tb = blockIdx.z;
    int tx = threadIdx.x & 31, ty = threadIdx.x >> 5;
    const float* xb = x + (size_t)tb * C_ * N_;
    #pragma unroll
    for (int j = 0; j < 4; j++)
        tile[ty + 8*j][tx] = xb[(size_t)(c0 + ty + 8*j) * N_ + n0 + tx];
    __syncthreads();
    #pragma unroll
    for (int j = 0; j < 4; j++) {
        int n = n0 + ty + 8*j, c = c0 + tx;
        float v = tile[tx][ty + 8*j];
        size_t idx = ((size_t)tb * N_ + n) * C_ + c;
        split2h(v, g_xsp[0][idx], g_xsp[1][idx]);
    }
}

// ---------------- fused GEMM + BN + LIF (t-sequential, vmem in SMEM) ----------
// blockIdx.z = b. 2-stage cp.async pipeline (40KB) + 64KB smem membrane state
// => 104KB/CTA, 2 CTAs/SM (16 warps). Mainloop identical to the proven kernel.
// EPI=0: u8 spikes to OutPtr (qkv -> attention path)
// EPI=1: fp16 spikes to OutPtr (fc1 -> fc2 GEMM operand)
template<int KTOT, int NT, int EPI>
__global__ __launch_bounds__(256, 2)
void gemm_lif(const __half* __restrict__ Act, size_t actStride,
              const __half* __restrict__ Wt, size_t wStride,
              void* __restrict__ OutPtr, int Mtot,
              const float* __restrict__ alpha, const float* __restrict__ offv,
              const float* __restrict__ beta)
{
    constexpr int KC   = KTOT / 32;
    constexpr int NSEG = NT * KC;
    constexpr int PITCH  = 80;
    constexpr int TILEB  = 128 * PITCH;     // 10240
    constexpr int STAGEB = 2 * TILEB;       // 20480
    constexpr int VMOFF  = 2 * STAGEB;      // 40960

    extern __shared__ char smem[];
    const uint32_t sb = smem_u32(smem);
    float* vm = (float*)(smem + VMOFF);     // vm[slot*256 + tid], 64 slots
    const int tid  = threadIdx.x;
    const int lane = tid & 31, warp = tid >> 5;
    const int wn = warp & 1, wm = warp >> 1;
    const int n0 = blockIdx.x * 128, m0 = blockIdx.y * 128;
    const int bz = blockIdx.z;

    const int WA3[3] = {1,0,0};
    const int XB3[3] = {0,1,0};
    const int WA2[2] = {1,0};
    const int XB2[2] = {0,0};

    const int r_ = tid >> 2, c_ = tid & 3;
    const int group = lane >> 2, tig = lane & 3;

    int tb = bz;
    auto load = [&](int seg, int st) {
        if (seg < NSEG) {
            int term = seg / KC, kc = seg - term * KC;
            int wa = (NT == 3) ? WA3[term] : WA2[term];
            int xb = (NT == 3) ? XB3[term] : XB2[term];
            const __half* ap = Act + (size_t)xb * actStride
                          + ((size_t)tb * N_ + n0) * KTOT + kc * 32;
            const __half* wp = Wt + (size_t)wa * wStride + (size_t)m0 * KTOT + kc * 32;
            uint32_t ab = sb + st * STAGEB, bbs = ab + TILEB;
            #pragma unroll
            for (int j = 0; j < 2; j++) {
                int r = r_ + j * 64;
                CP_ASYNC16(ab  + r * PITCH + c_ * 16, ap + (size_t)r * KTOT + c_ * 8);
                CP_ASYNC16(bbs + r * PITCH + c_ * 16, wp + (size_t)r * KTOT + c_ * 8);
            }
        }
        CP_COMMIT();
    };

    for (int t = 0; t < T_; t++) {
        tb = t * B_ + bz;

        float acc[4][4][4];
        #pragma unroll
        for (int i = 0; i < 4; i++)
            #pragma unroll
            for (int j = 0; j < 4; j++)
                #pragma unroll
                for (int v = 0; v < 4; v++) acc[i][j][v] = 0.0f;

        load(0, 0);

        for (int seg = 0; seg < NSEG; ++seg) {
            CP_WAIT(0);
            __syncthreads();
            load(seg + 1, (seg + 1) & 1);

            uint32_t ab = sb + (seg & 1) * STAGEB, bbs = ab + TILEB;
            #pragma unroll
            for (int ki = 0; ki < 2; ki++) {
                uint32_t a[4][4];
                #pragma unroll
                for (int ni = 0; ni < 4; ni++) {
                    int row = wn * 64 + ni * 16 + (lane & 15);
                    int cc  = ki * 2 + (lane >> 4);
                    uint32_t ad = ab + row * PITCH + cc * 16;
                    asm volatile("ldmatrix.sync.aligned.m8n8.x4.shared.b16 {%0,%1,%2,%3}, [%4];"
                        : "=r"(a[ni][0]), "=r"(a[ni][1]), "=r"(a[ni][2]), "=r"(a[ni][3])
                        : "r"(ad));
                }
                uint32_t b[4][2];
                #pragma unroll
                for (int mi2 = 0; mi2 < 2; mi2++) {
                    int row = wm * 32 + mi2 * 16 + (lane & 7) + ((lane >> 4) << 3);
                    int cc  = ki * 2 + ((lane >> 3) & 1);
                    uint32_t bd = bbs + row * PITCH + cc * 16;
                    uint32_t r0, r1, r2, r3;
                    asm volatile("ldmatrix.sync.aligned.m8n8.x4.shared.b16 {%0,%1,%2,%3}, [%4];"
                        : "=r"(r0), "=r"(r1), "=r"(r2), "=r"(r3) : "r"(bd));
                    b[mi2*2+0][0] = r0; b[mi2*2+0][1] = r1;
                    b[mi2*2+1][0] = r2; b[mi2*2+1][1] = r3;
                }
                #pragma unroll
                for (int ni = 0; ni < 4; ni++)
                    #pragma unroll
                    for (int mi = 0; mi < 4; mi++)
                        mma_f16(acc[ni][mi], a[ni], b[mi]);
            }
        }

        // ---- fused BN + LIF epilogue (membrane state in smem, per-thread) ----
        #pragma unroll
        for (int mi = 0; mi < 4; mi++) {
            int m = m0 + wm * 32 + mi * 8 + tig * 2;
            float2 al = *(const float2*)&alpha[m];
            float2 of = *(const float2*)&offv[m];
            float2 be = *(const float2*)&beta[m];
            #pragma unroll
            for (int ni = 0; ni < 4; ni++)
                #pragma unroll
                for (int vv = 0; vv < 2; vv++) {
                    int n = n0 + wn * 64 + ni * 16 + group + vv * 8;
                    float p0 = al.x * (acc[ni][mi][vv*2+0] + of.x) + be.x;
                    float p1 = al.y * (acc[ni][mi][vv*2+1] + of.y) + be.y;
                    int s = (mi * 4 + ni) * 4 + vv * 2;
                    float v0 = (t == 0) ? 0.0f : vm[s * 256 + tid];
                    float v1 = (t == 0) ? 0.0f : vm[(s + 1) * 256 + tid];
                    v0 = v0 + (p0 - v0) * 0.5f;
                    v1 = v1 + (p1 - v1) * 0.5f;
                    float s0 = (v0 >= 1.0f) ? 1.0f : 0.0f;
                    float s1 = (v1 >= 1.0f) ? 1.0f : 0.0f;
                    if (s0 != 0.0f) v0 = 0.0f;
                    if (s1 != 0.0f) v1 = 0.0f;
                    vm[s * 256 + tid] = v0;
                    vm[(s + 1) * 256 + tid] = v1;
                    if (EPI == 0) {
                        uchar2 pk;
                        pk.x = (uint8_t)(s0 != 0.0f ? 1 : 0);
                        pk.y = (uint8_t)(s1 != 0.0f ? 1 : 0);
                        *(uchar2*)&((uint8_t*)OutPtr)[((size_t)tb * N_ + n) * Mtot + m] = pk;
                    } else {
                        *(__half2*)&((__half*)OutPtr)[((size_t)tb * N_ + n) * Mtot + m] =
                            __floats2half2_rn(s0, s1);
                    }
                }
        }
    }
}

// ---------------- unfused mma.sync fp16 split-GEMM (4-stage, proj/fc2) --------
template<int KTOT, int NT>
__global__ __launch_bounds__(256)
void gemm_mma(const __half* __restrict__ Act, size_t actStride,
              const __half* __restrict__ Wt, size_t wStride,
              float* __restrict__ Y, int Mtot,
              const float* __restrict__ alpha, const float* __restrict__ offv,
              const float* __restrict__ beta)
{
    constexpr int KC   = KTOT / 32;
    constexpr int NSEG = NT * KC;
    constexpr int PITCH  = 80;
    constexpr int TILEB  = 128 * PITCH;
    constexpr int STAGEB = 2 * TILEB;
    constexpr int NSTAGE = 4;

    extern __shared__ char smem[];
    const uint32_t sb = smem_u32(smem);
    const int tid  = threadIdx.x;
    const int lane = tid & 31, warp = tid >> 5;
    const int wn = warp & 1, wm = warp >> 1;
    const int n0 = blockIdx.x * 128, m0 = blockIdx.y * 128;
    const int tbz = blockIdx.z;

    const int WA3[3] = {1,0,0};
    const int XB3[3] = {0,1,0};
    const int WA2[2] = {1,0};
    const int XB2[2] = {0,0};

    const int r_ = tid >> 2, c_ = tid & 3;

    auto load = [&](int seg, int st) {
        if (seg < NSEG) {
            int term = seg / KC, kc = seg - term * KC;
            int wa = (NT == 3) ? WA3[term] : WA2[term];
            int xb = (NT == 3) ? XB3[term] : XB2[term];
            const __half* ap = Act + (size_t)xb * actStride
                          + ((size_t)tbz * N_ + n0) * KTOT + kc * 32;
            const __half* wp = Wt + (size_t)wa * wStride + (size_t)m0 * KTOT + kc * 32;
            uint32_t ab = sb + st * STAGEB, bbs = ab + TILEB;
            #pragma unroll
            for (int j = 0; j < 2; j++) {
                int r = r_ + j * 64;
                CP_ASYNC16(ab  + r * PITCH + c_ * 16, ap + (size_t)r * KTOT + c_ * 8);
                CP_ASYNC16(bbs + r * PITCH + c_ * 16, wp + (size_t)r * KTOT + c_ * 8);
            }
        }
        CP_COMMIT();
    };

    float acc[4][4][4];
    #pragma unroll
    for (int i = 0; i < 4; i++)
        #pragma unroll
        for (int j = 0; j < 4; j++)
            #pragma unroll
            for (int v = 0; v < 4; v++) acc[i][j][v] = 0.0f;

    load(0, 0);
    load(1, 1);
    load(2, 2);

    for (int seg = 0; seg < NSEG; ++seg) {
        CP_WAIT(2);
        __syncthreads();
        load(seg + 3, (seg + 3) % NSTAGE);

        uint32_t ab = sb + (seg % NSTAGE) * STAGEB, bbs = ab + TILEB;
        #pragma unroll
        for (int ki = 0; ki < 2; ki++) {
            uint32_t a[4][4];
            #pragma unroll
            for (int ni = 0; ni < 4; ni++) {
                int row = wn * 64 + ni * 16 + (lane & 15);
                int cc  = ki * 2 + (lane >> 4);
                uint32_t ad = ab + row * PITCH + cc * 16;
                asm volatile("ldmatrix.sync.aligned.m8n8.x4.shared.b16 {%0,%1,%2,%3}, [%4];"
                    : "=r"(a[ni][0]), "=r"(a[ni][1]), "=r"(a[ni][2]), "=r"(a[ni][3])
                    : "r"(ad));
            }
            uint32_t b[4][2];
            #pragma unroll
            for (int mi2 = 0; mi2 < 2; mi2++) {
                int row = wm * 32 + mi2 * 16 + (lane & 7) + ((lane >> 4) << 3);
                int cc  = ki * 2 + ((lane >> 3) & 1);
                uint32_t bd = bbs + row * PITCH + cc * 16;
                uint32_t r0, r1, r2, r3;
                asm volatile("ldmatrix.sync.aligned.m8n8.x4.shared.b16 {%0,%1,%2,%3}, [%4];"
                    : "=r"(r0), "=r"(r1), "=r"(r2), "=r"(r3) : "r"(bd));
                b[mi2*2+0][0] = r0; b[mi2*2+0][1] = r1;
                b[mi2*2+1][0] = r2; b[mi2*2+1][1] = r3;
            }
            #pragma unroll
            for (int ni = 0; ni < 4; ni++)
                #pragma unroll
                for (int mi = 0; mi < 4; mi++)
                    mma_f16(acc[ni][mi], a[ni], b[mi]);
        }
    }

    const int group = lane >> 2, tig = lane & 3;
    #pragma unroll
    for (int mi = 0; mi < 4; mi++) {
        int m = m0 + wm * 32 + mi * 8 + tig * 2;
        float2 al = *(const float2*)&alpha[m];
        float2 of = *(const float2*)&offv[m];
        float2 be = *(const float2*)&beta[m];
        #pragma unroll
        for (int ni = 0; ni < 4; ni++)
            #pragma unroll
            for (int v = 0; v < 2; v++) {
                int n = n0 + wn * 64 + ni * 16 + group + v * 8;
                float2 val;
                val.x = al.x * (acc[ni][mi][v*2+0] + of.x) + be.x;
                val.y = al.y * (acc[ni][mi][v*2+1] + of.y) + be.y;
                *(float2*)&Y[((size_t)tbz * N_ + n) * Mtot + m] = val;
            }
    }
}

// ---------------- remaining LIF kernels ---------------------------------------
// x1 = (xsp0+xsp1) + spike(p); write fp16 2-split of x1
__global__ void lif_add_split4(const float* __restrict__ p, size_t S)
{
    size_t base = ((size_t)blockIdx.x * blockDim.x + threadIdx.x) * 4;
    if (base >= S) return;
    float v0 = 0.f, v1 = 0.f, v2 = 0.f, v3 = 0.f;
    #pragma unroll
    for (int t = 0; t < T_; t++) {
        size_t idx = (size_t)t * S + base;
        float4 pp = *(const float4*)&p[idx];
        uint2 xh0 = *(const uint2*)&g_xsp[0][idx];
        uint2 xh1 = *(const uint2*)&g_xsp[1][idx];
        __half2 xa0 = *reinterpret_cast<__half2*>(&xh0.x);
        __half2 xa1 = *reinterpret_cast<__half2*>(&xh0.y);
        __half2 xb0 = *reinterpret_cast<__half2*>(&xh1.x);
        __half2 xb1 = *reinterpret_cast<__half2*>(&xh1.y);
        float x0 = __half2float(__low2half(xa0))  + __half2float(__low2half(xb0));
        float x1v = __half2float(__high2half(xa0)) + __half2float(__high2half(xb0));
        float x2 = __half2float(__low2half(xa1))  + __half2float(__low2half(xb1));
        float x3 = __half2float(__high2half(xa1)) + __half2float(__high2half(xb1));
        v0 = v0 + (pp.x - v0) * 0.5f;
        v1 = v1 + (pp.y - v1) * 0.5f;
        v2 = v2 + (pp.z - v2) * 0.5f;
        v3 = v3 + (pp.w - v3) * 0.5f;
        float s0 = (v0 >= 1.f) ? 1.f : 0.f;
        float s1 = (v1 >= 1.f) ? 1.f : 0.f;
        float s2 = (v2 >= 1.f) ? 1.f : 0.f;
        float s3 = (v3 >= 1.f) ? 1.f : 0.f;
        if (s0 != 0.f) v0 = 0.f;
        if (s1 != 0.f) v1 = 0.f;
        if (s2 != 0.f) v2 = 0.f;
        if (s3 != 0.f) v3 = 0.f;
        float4 X = make_float4(x0 + s0, x1v + s1, x2 + s2, x3 + s3);
        __half a0, b0, a1, b1, a2, b2, a3, b3;
        split2h(X.x, a0, b0); split2h(X.y, a1, b1);
        split2h(X.z, a2, b2); split2h(X.w, a3, b3);
        *(uint2*)&g_ps[0][idx] = make_uint2(h2u(__halves2half2(a0, a1)),
                                            h2u(__halves2half2(a2, a3)));
        *(uint2*)&g_ps[1][idx] = make_uint2(h2u(__halves2half2(b0, b1)),
                                            h2u(__halves2half2(b2, b3)));
    }
}

// out[t,b,c,n] = x1 + spike(y2); x1 = ps0 + ps1
__global__ void lif_final_t(float* __restrict__ out)
{
    __shared__ float st[32][33];
    int c0 = blockIdx.x * 32, n0 = blockIdx.y * 32, b = blockIdx.z;
    int tx = threadIdx.x & 31, ty = threadIdx.x >> 5;
    float v[4] = {0.f, 0.f, 0.f, 0.f};
    for (int t = 0; t < T_; t++) {
        int tb = t * B_ + b;
        #pragma unroll
        for (int j = 0; j < 4; j++) {
            int n = n0 + ty + 8*j;
            size_t idx = ((size_t)tb * N_ + n) * C_ + c0 + tx;
            float y = g_y2[idx];
            v[j] = v[j] + (y - v[j]) * 0.5f;
            float s = (v[j] >= 1.f) ? 1.f : 0.f;
            if (s != 0.f) v[j] = 0.f;
            float x1 = __half2float(g_ps[0][idx]) + __half2float(g_ps[1][idx]);
            st[tx][ty + 8*j] = x1 + s;
        }
        __syncthreads();
        #pragma unroll
        for (int j = 0; j < 4; j++) {
            int c = c0 + ty + 8*j;
            out[(((size_t)t * B_ + b) * C_ + c) * N_ + n0 + tx] = st[ty + 8*j][tx];
        }
        __syncthreads();
    }
}

// ---------------- attention stage 1: kv = k^T v per (tb,h) (u8 spikes) --------
__global__ __launch_bounds__(256) void attn_kv()
{
    int blk = blockIdx.x;
    int h  = blk & 7;
    int tb = blk >> 3;
    const uint8_t* base = g_qkvu + (size_t)tb * N_ * 768;

    __shared__ float ks[128][33];
    __shared__ float vs[128][36];

    int tid = threadIdx.x;
    int d  = tid >> 3;
    int e4 = (tid & 7) * 4;
    float acc[4] = {0.f, 0.f, 0.f, 0.f};

    for (int n0 = 0; n0 < N_; n0 += 128) {
        for (int i = tid; i < 128 * 32; i += 256) {
            int nl = i >> 5, dd = i & 31;
            const uint8_t* row = base + (size_t)(n0 + nl) * 768 + h * 32;
            ks[nl][dd] = (float)row[256 + dd];
            vs[nl][dd] = (float)row[512 + dd];
        }
        __syncthreads();
        for (int n = 0; n < 128; n++) {
            float kd = ks[n][d];
            float4 vv = *(const float4*)&vs[n][e4];
            acc[0] += kd * vv.x; acc[1] += kd * vv.y;
            acc[2] += kd * vv.z; acc[3] += kd * vv.w;
        }
        __syncthreads();
    }
    float* o = g_kv + (size_t)blk * 1024 + d * 32 + e4;
    o[0] = acc[0]; o[1] = acc[1]; o[2] = acc[2]; o[3] = acc[3];
}

// ---------------- attention stage 2: a = q·kv + fused vth=0.5 LIF -------------
__global__ __launch_bounds__(256) void attn_apply()
{
    __shared__ float kvs[8 * 32 * 32];
    int nc = blockIdx.x, b = blockIdx.y;
    int nl = threadIdx.x & 31, h = threadIdx.x >> 5;
    int n  = nc * 32 + nl;
    int tid = threadIdx.x;

    float v[32];
    #pragma unroll
    for (int e = 0; e < 32; e++) v[e] = 0.f;

    for (int t = 0; t < T_; t++) {
        int tb = t * B_ + b;
        for (int i = tid; i < 8 * 1024; i += 256)
            kvs[i] = g_kv[(size_t)(tb * 8) * 1024 + i];
        __syncthreads();

        uint4 qr[2];
        const uint4* qp = (const uint4*)(g_qkvu + ((size_t)tb * N_ + n) * 768 + h * 32);
        qr[0] = qp[0]; qr[1] = qp[1];
        const uint8_t* qv = (const uint8_t*)qr;

        float a[32];
        #pragma unroll
        for (int e = 0; e < 32; e++) a[e] = 0.f;
        #pragma unroll 4
        for (int d = 0; d < 32; d++) {
            if (qv[d] != 0) {
                const float4* kr = (const float4*)&kvs[h * 1024 + d * 32];
                #pragma unroll
                for (int e4 = 0; e4 < 8; e4++) {
                    float4 kk = kr[e4];
                    a[e4*4+0] += kk.x; a[e4*4+1] += kk.y;
                    a[e4*4+2] += kk.z; a[e4*4+3] += kk.w;
                }
            }
        }

        uint32_t pk[16];
        #pragma unroll
        for (int e2 = 0; e2 < 16; e2++) {
            int e0 = e2 * 2, e1 = e2 * 2 + 1;
            float aa0 = a[e0] * 0.125f;
            float aa1 = a[e1] * 0.125f;
            v[e0] = v[e0] + (aa0 - v[e0]) * 0.5f;
            v[e1] = v[e1] + (aa1 - v[e1]) * 0.5f;
            float s0 = (v[e0] >= 0.5f) ? 1.f : 0.f;
            float s1 = (v[e1] >= 0.5f) ? 1.f : 0.f;
            if (s0 != 0.f) v[e0] = 0.f;
            if (s1 != 0.f) v[e1] = 0.f;
            pk[e2] = h2u(__floats2half2_rn(s0, s1));
        }
        uint4* dst = (uint4*)(g_ab + ((size_t)tb * N_ + n) * 256 + h * 32);
        dst[0] = make_uint4(pk[0],  pk[1],  pk[2],  pk[3]);
        dst[1] = make_uint4(pk[4],  pk[5],  pk[6],  pk[7]);
        dst[2] = make_uint4(pk[8],  pk[9],  pk[10], pk[11]);
        dst[3] = make_uint4(pk[12], pk[13], pk[14], pk[15]);
        __syncthreads();
    }
}

// ---------------- launch -----------------------------------------------------
extern "C" void kernel_launch(void* const* d_in, const int* in_sizes, int n_in,
                              void* d_out, int out_size)
{
    const float* x       = (const float*)d_in[0];
    const float* wq      = (const float*)d_in[2];
    const float* bn_q    = (const float*)d_in[3];
    const float* wk      = (const float*)d_in[4];
    const float* bn_k    = (const float*)d_in[5];
    const float* wv      = (const float*)d_in[6];
    const float* bn_v    = (const float*)d_in[7];
    const float* w_proj  = (const float*)d_in[8];
    const float* b_proj  = (const float*)d_in[9];
    const float* bn_proj = (const float*)d_in[10];
    const float* w_fc1   = (const float*)d_in[11];
    const float* b_fc1   = (const float*)d_in[12];
    const float* bn_fc1  = (const float*)d_in[13];
    const float* w_fc2   = (const float*)d_in[14];
    const float* b_fc2   = (const float*)d_in[15];
    const float* bn_fc2  = (const float*)d_in[16];
    float* out = (float*)d_out;

    __half *wr, *xsp, *ps, *wpb, *wf2b, *ab, *h1b;
    uint8_t *qkvu;
    float *p, *y2, *al, *of, *be;
    cudaGetSymbolAddress((void**)&wr,   g_wr);
    cudaGetSymbolAddress((void**)&wpb,  g_wpb);
    cudaGetSymbolAddress((void**)&wf2b, g_wf2b);
    cudaGetSymbolAddress((void**)&xsp,  g_xsp);
    cudaGetSymbolAddress((void**)&ps,   g_ps);
    cudaGetSymbolAddress((void**)&ab,   g_ab);
    cudaGetSymbolAddress((void**)&h1b,  g_h1b);
    cudaGetSymbolAddress((void**)&qkvu, g_qkvu);
    cudaGetSymbolAddress((void**)&p,    g_p);
    cudaGetSymbolAddress((void**)&y2,   g_y2);
    cudaGetSymbolAddress((void**)&al,   g_alpha);
    cudaGetSymbolAddress((void**)&of,   g_off);
    cudaGetSymbolAddress((void**)&be,   g_beta);

    const int SMEM  = 4 * 20480;                 // 81920 (unfused, 4-stage)
    const int SMEMF = 2 * 20480 + 65536;         // 106496 (fused: 2-stage + vmem)
    cudaFuncSetAttribute(gemm_lif<256,3,0>,
                         cudaFuncAttributeMaxDynamicSharedMemorySize, SMEMF);
    cudaFuncSetAttribute(gemm_lif<256,3,1>,
                         cudaFuncAttributeMaxDynamicSharedMemorySize, SMEMF);
    cudaFuncSetAttribute(gemm_mma<256,2>,
                         cudaFuncAttributeMaxDynamicSharedMemorySize, SMEM);
    cudaFuncSetAttribute(gemm_mma<1024,2>,
                         cudaFuncAttributeMaxDynamicSharedMemorySize, SMEM);

    prep_aff<<<1, 256>>>(bn_q, bn_k, bn_v, b_proj, bn_proj, b_fc1, bn_fc1, b_fc2, bn_fc2);
    prep_w_real<<<(WR_SZ + 255)/256, 256>>>(wq, wk, wv, w_fc1);
    prep_w_bin<<<(65536 + 262144 + 255)/256, 256>>>(w_proj, w_fc2);
    transpose_split<<<dim3(8, 32, TB_), 256>>>(x);

    // qkv: fused GEMM+BN+LIF -> u8 spikes (no preact round-trip)
    gemm_lif<256,3,0><<<dim3(8, 6, B_), 256, SMEMF>>>(
        xsp, TCN, wr, WR_SZ, qkvu, 768, al + AOFF_QKV, of + AOFF_QKV, be + AOFF_QKV);

    // attention
    attn_kv<<<TB_ * HEADS_, 256>>>();
    attn_apply<<<dim3(N_/32, B_), 256>>>();

    // proj: unfused (epilogue feeds residual+split kernel)
    gemm_mma<256,2><<<dim3(8, 2, TB_), 256, SMEM>>>(
        ab, 0, wpb, 65536, p, 256, al + AOFF_P, of + AOFF_P, be + AOFF_P);
    lif_add_split4<<<(int)(S_C/4/256), 256>>>(p, S_C);

    // fc1: fused GEMM+BN+LIF -> fp16 spikes (no preact round-trip)
    gemm_lif<256,3,1><<<dim3(8, 8, B_), 256, SMEMF>>>(
        ps, TCN, wr + 768*256, WR_SZ, h1b, 1024, al + AOFF_F1, of + AOFF_F1, be + AOFF_F1);

    // fc2: unfused
    gemm_mma<1024,2><<<dim3(8, 2, TB_), 256, SMEM>>>(
        h1b, 0, wf2b, 262144, y2, 256, al + AOFF_F2, of + AOFF_F2, be + AOFF_F2);
    lif_final_t<<<dim3(C_/32, N_/32, B_), 256>>>(out);
}